// round 9
// baseline (speedup 1.0000x reference)
#include <cuda_runtime.h>
#include <math.h>
#include <stdint.h>

// Problem constants
#define M1    16384     // B*T*HW rows
#define CDIM  512
#define N1    1536      // 3*C
#define NH    8
#define HD    64
#define TT    16
#define HWDIM 1024
#define NPROB 128       // NH * TT

// Scratch (allocation-free rule: __device__ globals)
__device__ float g_q[(size_t)NPROB * HWDIM * HD];   // [p][hw][d], tf32, pre-scaled 1/8
__device__ float g_k[(size_t)NPROB * HWDIM * HD];   // [p][key][perm(d)]
__device__ float g_vt[(size_t)NPROB * HD * HWDIM];  // [p][d][perm(key)]
__device__ float g_att[(size_t)M1 * CDIM];          // [m][perm8(k)] interleaved
__device__ float g_xc[(size_t)M1 * CDIM];           // tf32 x, [m][perm8(k)]
__device__ float g_wqkvt[(size_t)N1 * CDIM];        // tf32 Wqkv^T [n][perm8(k)]
__device__ float g_woutt[(size_t)CDIM * CDIM];      // tf32 Wout^T [n][perm8(k)]

// ---------------------------------------------------------------------------
// helpers
// ---------------------------------------------------------------------------
__device__ __forceinline__ float to_tf32(float x) {
    unsigned r;
    asm("cvt.rna.tf32.f32 %0, %1;" : "=r"(r) : "f"(x));
    return __uint_as_float(r);
}

__device__ __forceinline__ void mma8(float c[4],
                                     float a0, float a1, float a2, float a3,
                                     float b0, float b1) {
    asm volatile(
        "mma.sync.aligned.m16n8k8.row.col.f32.tf32.tf32.f32 "
        "{%0,%1,%2,%3}, {%4,%5,%6,%7}, {%8,%9}, {%0,%1,%2,%3};\n"
        : "+f"(c[0]), "+f"(c[1]), "+f"(c[2]), "+f"(c[3])
        : "r"(__float_as_uint(a0)), "r"(__float_as_uint(a1)),
          "r"(__float_as_uint(a2)), "r"(__float_as_uint(a3)),
          "r"(__float_as_uint(b0)), "r"(__float_as_uint(b1)));
}

__device__ __forceinline__ unsigned smem_u32(const void* p) {
    return (unsigned)__cvta_generic_to_shared(p);
}
__device__ __forceinline__ void cp16(unsigned dst, const void* src) {
    asm volatile("cp.async.cg.shared.global [%0], [%1], 16;" :: "r"(dst), "l"(src));
}
__device__ __forceinline__ void cp_commit() {
    asm volatile("cp.async.commit_group;");
}
template <int N>
__device__ __forceinline__ void cp_wait() {
    asm volatile("cp.async.wait_group %0;" :: "n"(N));
}

// within-8-block interleave: (t, t+4) -> (2t, 2t+1)
__device__ __forceinline__ int perm8(int j) {
    return ((j & 3) << 1) | ((j >> 2) & 1);
}
__device__ __forceinline__ int P8(int d) {
    return (d & ~7) | perm8(d & 7);
}

// ---------------------------------------------------------------------------
// prepass: tf32 cvt + K-interleave (x), and cvt + transpose + K-interleave (W)
// ---------------------------------------------------------------------------
__global__ void cvt_il_scalar(const float* __restrict__ in,
                              float* __restrict__ out, int rowlen, int n)
{
    int i = blockIdx.x * blockDim.x + threadIdx.x;
    if (i < n) {
        int r = i / rowlen, k = i % rowlen;
        out[(size_t)r * rowlen + (k & ~7) + perm8(k & 7)] = to_tf32(in[i]);
    }
}

__global__ __launch_bounds__(256) void cvt_trans_kernel(
    const float* __restrict__ in, float* __restrict__ out, int K, int N)
{
    __shared__ float t[32][33];
    int n0 = blockIdx.x * 32, k0 = blockIdx.y * 32;
    int tx = threadIdx.x & 31, ty = threadIdx.x >> 5;
#pragma unroll
    for (int r = 0; r < 4; ++r)
        t[ty + r * 8][tx] = in[(size_t)(k0 + ty + r * 8) * N + n0 + tx];
    __syncthreads();
#pragma unroll
    for (int r = 0; r < 4; ++r) {
        int k = k0 + tx;
        out[(size_t)(n0 + ty + r * 8) * K + (k & ~7) + perm8(k & 7)] =
            to_tf32(t[tx][ty + r * 8]);
    }
}

// ---------------------------------------------------------------------------
// TF32 TC GEMM, warp tile 64x64, interleaved-K LDS.64 operands.
// A[m][perm8 k] (M x K), B[n][perm8 k] (N x K). C = A@B^T + bias.
// Block: 128 x BN, NWARP warps (wm = warp&1 -> 64 m, wn = warp>>1 -> 64 n).
// smem: A [128][40], B [BN][40], double-buffered.
// EPI==1: QKV scatter; EPI==2: Cout = acc + bias.
// ---------------------------------------------------------------------------
#define GSTR 40

template <int BN, int NWARP>
__device__ __forceinline__ void g_issue(
    const float* __restrict__ A, const float* __restrict__ B,
    float* As, int tid, int kt, int buf, int m0, int n0, int K)
{
    const int NT = NWARP * 32;
    float* Ad = As + buf * (128 + BN) * GSTR;
    float* Bd = Ad + 128 * GSTR;
#pragma unroll
    for (int i = 0; i < (128 + BN) * 8 / NT; ++i) {
        int idx = i * NT + tid;
        if (idx < 1024) {
            int r = idx >> 3, c = idx & 7;
            cp16(smem_u32(Ad + r * GSTR + c * 4),
                 A + (size_t)(m0 + r) * K + kt * 32 + c * 4);
        } else {
            int j = idx - 1024;
            int r = j >> 3, c = j & 7;
            cp16(smem_u32(Bd + r * GSTR + c * 4),
                 B + (size_t)(n0 + r) * K + kt * 32 + c * 4);
        }
    }
    cp_commit();
}

template <int EPI, int BN, int NWARP>
__global__ __launch_bounds__(NWARP * 32) void sgemm_tc(
    const float* __restrict__ A, const float* __restrict__ B,
    const float* __restrict__ bias, float* __restrict__ Cout,
    int N, int K)
{
    extern __shared__ float sh[];

    const int tid  = threadIdx.x;
    const int warp = tid >> 5;
    const int lane = tid & 31;
    const int g    = lane >> 2;
    const int tg   = lane & 3;
    const int wm   = warp & 1;
    const int wn   = warp >> 1;
    const int m0   = blockIdx.y * 128;
    const int n0   = blockIdx.x * BN;

    float acc[4][8][4];
#pragma unroll
    for (int i = 0; i < 4; ++i)
#pragma unroll
        for (int j = 0; j < 8; ++j)
#pragma unroll
            for (int r = 0; r < 4; ++r) acc[i][j][r] = 0.0f;

    const int NTILE = K >> 5;
    g_issue<BN, NWARP>(A, B, sh, tid, 0, 0, m0, n0, K);

    for (int kt = 0; kt < NTILE; ++kt) {
        if (kt + 1 < NTILE) {
            g_issue<BN, NWARP>(A, B, sh, tid, kt + 1, (kt + 1) & 1, m0, n0, K);
            cp_wait<1>();
        } else {
            cp_wait<0>();
        }
        __syncthreads();

        const float* Ab = sh + (kt & 1) * (128 + BN) * GSTR;
        const float* Bb = Ab + 128 * GSTR;
#pragma unroll
        for (int ks = 0; ks < 4; ++ks) {
            int kk2 = ks * 8 + 2 * tg;
            float2 a[4][2];
            float2 b[8];
#pragma unroll
            for (int mt = 0; mt < 4; ++mt) {
                int m = wm * 64 + mt * 16 + g;
                a[mt][0] = *(const float2*)(Ab + m * GSTR + kk2);
                a[mt][1] = *(const float2*)(Ab + (m + 8) * GSTR + kk2);
            }
#pragma unroll
            for (int nt = 0; nt < 8; ++nt) {
                int n = wn * 64 + nt * 8 + g;
                b[nt] = *(const float2*)(Bb + n * GSTR + kk2);
            }
#pragma unroll
            for (int mt = 0; mt < 4; ++mt)
#pragma unroll
                for (int nt = 0; nt < 8; ++nt)
                    mma8(acc[mt][nt], a[mt][0].x, a[mt][1].x,
                         a[mt][0].y, a[mt][1].y, b[nt].x, b[nt].y);
        }
        __syncthreads();
    }

    // ---- epilogue ----
    if (EPI == 1) {
#pragma unroll
        for (int mt = 0; mt < 4; ++mt) {
            int m  = m0 + wm * 64 + mt * 16 + g;
            int t  = m >> 10;
            int hw0 = m & 1023;
            int hw1 = (m + 8) & 1023;
#pragma unroll
            for (int nt = 0; nt < 8; ++nt) {
                int n   = n0 + wn * 64 + nt * 8 + 2 * tg;
                float2 bv = *(const float2*)(bias + n);
                int s   = n >> 9;
                int rem = n & 511;
                int h   = rem >> 6;
                int d   = rem & 63;          // even
                float v00 = acc[mt][nt][0] + bv.x;   // (hw0, d)
                float v01 = acc[mt][nt][1] + bv.y;   // (hw0, d+1)
                float v10 = acc[mt][nt][2] + bv.x;   // (hw1, d)
                float v11 = acc[mt][nt][3] + bv.y;   // (hw1, d+1)
                if (s == 0) {
                    size_t base = ((size_t)(h * 16 + t) * 1024) * 64 + d;
                    float2 v0, v1;
                    v0.x = to_tf32(v00 * 0.125f); v0.y = to_tf32(v01 * 0.125f);
                    v1.x = to_tf32(v10 * 0.125f); v1.y = to_tf32(v11 * 0.125f);
                    *(float2*)(g_q + base + (size_t)hw0 * 64) = v0;
                    *(float2*)(g_q + base + (size_t)hw1 * 64) = v1;
                } else if (s == 1) {
                    size_t base = ((size_t)(h * 16 + t) * 1024) * 64;
                    int p0 = P8(d), p1 = P8(d + 1);
                    g_k[base + (size_t)hw0 * 64 + p0] = to_tf32(v00);
                    g_k[base + (size_t)hw0 * 64 + p1] = to_tf32(v01);
                    g_k[base + (size_t)hw1 * 64 + p0] = to_tf32(v10);
                    g_k[base + (size_t)hw1 * 64 + p1] = to_tf32(v11);
                } else {
                    size_t base = ((size_t)(h * 16 + t) * 64) * 1024;
                    int b0 = (hw0 & ~7) | perm8(hw0 & 7);
                    int b1 = (hw1 & ~7) | perm8(hw1 & 7);
                    g_vt[base + (size_t)d * 1024 + b0]       = to_tf32(v00);
                    g_vt[base + (size_t)(d + 1) * 1024 + b0] = to_tf32(v01);
                    g_vt[base + (size_t)d * 1024 + b1]       = to_tf32(v10);
                    g_vt[base + (size_t)(d + 1) * 1024 + b1] = to_tf32(v11);
                }
            }
        }
    } else {
#pragma unroll
        for (int mt = 0; mt < 4; ++mt) {
            int m = m0 + wm * 64 + mt * 16 + g;
#pragma unroll
            for (int nt = 0; nt < 8; ++nt) {
                int n = n0 + wn * 64 + nt * 8 + 2 * tg;
                float2 bv = *(const float2*)(bias + n);
                float2 v0, v1;
                v0.x = acc[mt][nt][0] + bv.x;
                v0.y = acc[mt][nt][1] + bv.y;
                v1.x = acc[mt][nt][2] + bv.x;
                v1.y = acc[mt][nt][3] + bv.y;
                *(float2*)(Cout + (size_t)m * N + n)       = v0;
                *(float2*)(Cout + (size_t)(m + 8) * N + n) = v1;
            }
        }
    }
}

// ---------------------------------------------------------------------------
// Flash attention (TF32 mma.sync) — R7-proven; g_att store K-interleaved.
// ---------------------------------------------------------------------------
#define KVSTR 72
#define KVTILE (64 * KVSTR)

__device__ __forceinline__ void attn_issue(
    const float* __restrict__ Kg, const float* __restrict__ Vtg,
    float* Ks, float* Vs, int tid, int kt, int buf)
{
    float* Kd = Ks + buf * KVTILE;
    float* Vd = Vs + buf * KVTILE;
#pragma unroll
    for (int i = 0; i < 4; ++i) {
        int idx = i * 256 + tid;
        int r = idx >> 4, c4 = (idx & 15) << 2;
        cp16(smem_u32(Kd + r * KVSTR + c4), Kg + (size_t)(kt * 64 + r) * 64 + c4);
        cp16(smem_u32(Vd + r * KVSTR + c4), Vtg + (size_t)r * 1024 + kt * 64 + c4);
    }
    cp_commit();
}

__global__ __launch_bounds__(256, 2) void attn_kernel()
{
    extern __shared__ float sm[];
    float* Ks = sm;
    float* Vs = sm + 2 * KVTILE;

    const int p  = blockIdx.y;
    const int q0 = blockIdx.x * 128;
    const float* Qg  = g_q  + (size_t)p * HWDIM * HD;
    const float* Kg  = g_k  + (size_t)p * HWDIM * HD;
    const float* Vtg = g_vt + (size_t)p * HD * HWDIM;

    const int tid  = threadIdx.x;
    const int w    = tid >> 5;
    const int lane = tid & 31;
    const int g    = lane >> 2;
    const int tg   = lane & 3;
    const int m    = w * 16 + g;
    const int src1 = (lane & ~3) + (tg >> 1);
    const int src2 = src1 + 2;
    const bool hi  = (tg & 1);

    attn_issue(Kg, Vtg, Ks, Vs, tid, 0, 0);

    float Qr[8][4];
    {
        const float* Q0 = Qg + (size_t)(q0 + m) * HD;
        const float* Q1 = Q0 + 8 * HD;
#pragma unroll
        for (int o = 0; o < 8; ++o) {
            Qr[o][0] = __ldg(Q0 + o * 8 + tg);
            Qr[o][1] = __ldg(Q1 + o * 8 + tg);
            Qr[o][2] = __ldg(Q0 + o * 8 + tg + 4);
            Qr[o][3] = __ldg(Q1 + o * 8 + tg + 4);
        }
    }

    float O[8][4];
#pragma unroll
    for (int nt = 0; nt < 8; ++nt)
#pragma unroll
        for (int r = 0; r < 4; ++r) O[nt][r] = 0.0f;
    float mo[2] = {-1e30f, -1e30f};
    float l[2]  = {0.0f, 0.0f};

    for (int kt = 0; kt < 16; ++kt) {
        if (kt + 1 < 16) {
            attn_issue(Kg, Vtg, Ks, Vs, tid, kt + 1, (kt + 1) & 1);
            cp_wait<1>();
        } else {
            cp_wait<0>();
        }
        __syncthreads();
        const float* Kb = Ks + (kt & 1) * KVTILE;
        const float* Vb = Vs + (kt & 1) * KVTILE;

        float S[8][4];
#pragma unroll
        for (int nk = 0; nk < 8; ++nk)
#pragma unroll
            for (int r = 0; r < 4; ++r) S[nk][r] = 0.0f;
#pragma unroll
        for (int ks = 0; ks < 8; ++ks) {
            int kk = ks * 8;
#pragma unroll
            for (int nk = 0; nk < 8; ++nk) {
                float2 bk = *(const float2*)(Kb + (nk * 8 + g) * KVSTR + kk + 2 * tg);
                mma8(S[nk], Qr[ks][0], Qr[ks][1], Qr[ks][2], Qr[ks][3],
                     bk.x, bk.y);
            }
        }

        float mn[2] = {-1e30f, -1e30f};
#pragma unroll
        for (int nk = 0; nk < 8; ++nk) {
            mn[0] = fmaxf(mn[0], fmaxf(S[nk][0], S[nk][1]));
            mn[1] = fmaxf(mn[1], fmaxf(S[nk][2], S[nk][3]));
        }
#pragma unroll
        for (int s = 0; s < 2; ++s) {
            mn[s] = fmaxf(mn[s], __shfl_xor_sync(0xFFFFFFFFu, mn[s], 1));
            mn[s] = fmaxf(mn[s], __shfl_xor_sync(0xFFFFFFFFu, mn[s], 2));
            mn[s] = fmaxf(mn[s], mo[s]);
        }
        float al[2];
        al[0] = __expf(mo[0] - mn[0]);
        al[1] = __expf(mo[1] - mn[1]);
#pragma unroll
        for (int nt = 0; nt < 8; ++nt) {
            O[nt][0] *= al[0]; O[nt][1] *= al[0];
            O[nt][2] *= al[1]; O[nt][3] *= al[1];
        }
        float rs[2] = {0.0f, 0.0f};
#pragma unroll
        for (int nk = 0; nk < 8; ++nk) {
            float p0 = __expf(S[nk][0] - mn[0]);
            float p1 = __expf(S[nk][1] - mn[0]);
            float p2 = __expf(S[nk][2] - mn[1]);
            float p3 = __expf(S[nk][3] - mn[1]);
            rs[0] += p0 + p1;
            rs[1] += p2 + p3;
            S[nk][0] = to_tf32(p0);
            S[nk][1] = to_tf32(p1);
            S[nk][2] = to_tf32(p2);
            S[nk][3] = to_tf32(p3);
        }
#pragma unroll
        for (int s = 0; s < 2; ++s) {
            rs[s] += __shfl_xor_sync(0xFFFFFFFFu, rs[s], 1);
            rs[s] += __shfl_xor_sync(0xFFFFFFFFu, rs[s], 2);
            l[s] = l[s] * al[s] + rs[s];
            mo[s] = mn[s];
        }

#pragma unroll
        for (int ks = 0; ks < 8; ++ks) {
            float u0 = __shfl_sync(0xFFFFFFFFu, S[ks][0], src1);
            float u1 = __shfl_sync(0xFFFFFFFFu, S[ks][1], src1);
            float u2 = __shfl_sync(0xFFFFFFFFu, S[ks][2], src1);
            float u3 = __shfl_sync(0xFFFFFFFFu, S[ks][3], src1);
            float w0 = __shfl_sync(0xFFFFFFFFu, S[ks][0], src2);
            float w1 = __shfl_sync(0xFFFFFFFFu, S[ks][1], src2);
            float w2 = __shfl_sync(0xFFFFFFFFu, S[ks][2], src2);
            float w3 = __shfl_sync(0xFFFFFFFFu, S[ks][3], src2);
            float a0 = hi ? u1 : u0;
            float a1 = hi ? u3 : u2;
            float a2 = hi ? w1 : w0;
            float a3 = hi ? w3 : w2;
            int kk = ks * 8;
#pragma unroll
            for (int nt = 0; nt < 8; ++nt) {
                float2 bv = *(const float2*)(Vb + (nt * 8 + g) * KVSTR + kk + 2 * tg);
                mma8(O[nt], a0, a1, a2, a3, bv.x, bv.y);
            }
        }
        __syncthreads();
    }

    // ---- epilogue: normalize + permuted store, K-interleaved for sgemm2 ----
    const int h = p >> 4;
    const int t = p & 15;
    {
        int q = q0 + m;
        float inv0 = 1.0f / l[0];
        float inv1 = 1.0f / l[1];
        size_t base0 = ((size_t)(h * 1024 + q) * 16 + t) * 64;
        size_t base1 = ((size_t)(h * 1024 + q + 8) * 16 + t) * 64;
        int j0 = perm8(2 * tg), j1 = perm8(2 * tg + 1);
#pragma unroll
        for (int nt = 0; nt < 8; ++nt) {
            int d = nt * 8;
            g_att[base0 + d + j0] = to_tf32(O[nt][0] * inv0);
            g_att[base0 + d + j1] = to_tf32(O[nt][1] * inv0);
            g_att[base1 + d + j0] = to_tf32(O[nt][2] * inv1);
            g_att[base1 + d + j1] = to_tf32(O[nt][3] * inv1);
        }
    }
}

// ---------------------------------------------------------------------------
extern "C" void kernel_launch(void* const* d_in, const int* in_sizes, int n_in,
                              void* d_out, int out_size)
{
    const float* x    = (const float*)d_in[0];
    const float* Wqkv = (const float*)d_in[1];
    const float* bqkv = (const float*)d_in[2];
    const float* Wout = (const float*)d_in[3];
    const float* bout = (const float*)d_in[4];
    float* out = (float*)d_out;

    float *xc, *wqkvt, *woutt, *gatt_ptr;
    cudaGetSymbolAddress((void**)&xc, g_xc);
    cudaGetSymbolAddress((void**)&wqkvt, g_wqkvt);
    cudaGetSymbolAddress((void**)&woutt, g_woutt);
    cudaGetSymbolAddress((void**)&gatt_ptr, g_att);

    // 0) prepass: tf32 + K-interleave x; transpose + interleave weights
    cvt_il_scalar<<<(M1 * CDIM + 255) / 256, 256>>>(x, xc, CDIM, M1 * CDIM);
    cvt_trans_kernel<<<dim3(N1 / 32, CDIM / 32), 256>>>(Wqkv, wqkvt, CDIM, N1);
    cvt_trans_kernel<<<dim3(CDIM / 32, CDIM / 32), 256>>>(Wout, woutt, CDIM, CDIM);

    // 1) QKV projection: block 128x256, 8 warps
    const int smem1 = 2 * (128 + 256) * GSTR * (int)sizeof(float);
    cudaFuncSetAttribute((const void*)sgemm_tc<1, 256, 8>,
                         cudaFuncAttributeMaxDynamicSharedMemorySize, smem1);
    sgemm_tc<1, 256, 8><<<dim3(N1 / 256, M1 / 128), 256, smem1>>>(
        xc, wqkvt, bqkv, nullptr, N1, CDIM);

    // 2) flash attention
    const int attn_smem = 4 * KVTILE * (int)sizeof(float);
    cudaFuncSetAttribute(attn_kernel,
                         cudaFuncAttributeMaxDynamicSharedMemorySize, attn_smem);
    attn_kernel<<<dim3(HWDIM / 128, NPROB), 256, attn_smem>>>();

    // 3) output projection: block 128x128, 4 warps
    const int smem2 = 2 * (128 + 128) * GSTR * (int)sizeof(float);
    cudaFuncSetAttribute((const void*)sgemm_tc<2, 128, 4>,
                         cudaFuncAttributeMaxDynamicSharedMemorySize, smem2);
    sgemm_tc<2, 128, 4><<<dim3(CDIM / 128, M1 / 128), 128, smem2>>>(
        gatt_ptr, woutt, bout, out, CDIM, CDIM);
}

// round 10
// speedup vs baseline: 1.9155x; 1.9155x over previous
#include <cuda_runtime.h>
#include <cuda_fp16.h>
#include <math.h>
#include <stdint.h>

// Problem constants
#define M1    16384     // B*T*HW rows
#define CDIM  512
#define N1    1536      // 3*C
#define NH    8
#define HD    64
#define TT    16
#define HWDIM 1024
#define NPROB 128       // NH * TT
#define CU    256       // CDIM/2 (u32 half2 units)
#define HU    32        // HD/2

// Scratch (allocation-free rule: __device__ globals).  All half2-packed u32.
__device__ unsigned g_q[(size_t)NPROB * HWDIM * HU];    // [p][hw][d/2], pre-scaled 1/8
__device__ unsigned g_k[(size_t)NPROB * HWDIM * HU];    // [p][key][d/2]
__device__ unsigned g_vt[(size_t)NPROB * HD * (HWDIM/2)]; // [p][d][key/2]
__device__ unsigned g_atth[(size_t)M1 * CU];            // [m][k/2] for sgemm2
__device__ unsigned g_xh[(size_t)M1 * CU];              // x packed [m][k/2]
__device__ unsigned g_wqkvh[(size_t)N1 * CU];           // Wqkv^T packed [n][k/2]
__device__ unsigned g_wouth[(size_t)CDIM * CU];         // Wout^T packed [n][k/2]

// ---------------------------------------------------------------------------
// helpers
// ---------------------------------------------------------------------------
__device__ __forceinline__ unsigned packh2(float x, float y) {
    __half2 h = __floats2half2_rn(x, y);
    return *reinterpret_cast<unsigned*>(&h);
}

__device__ __forceinline__ void mma16(float c[4],
                                      unsigned a0, unsigned a1, unsigned a2,
                                      unsigned a3, unsigned b0, unsigned b1) {
    asm volatile(
        "mma.sync.aligned.m16n8k16.row.col.f32.f16.f16.f32 "
        "{%0,%1,%2,%3}, {%4,%5,%6,%7}, {%8,%9}, {%0,%1,%2,%3};\n"
        : "+f"(c[0]), "+f"(c[1]), "+f"(c[2]), "+f"(c[3])
        : "r"(a0), "r"(a1), "r"(a2), "r"(a3), "r"(b0), "r"(b1));
}

__device__ __forceinline__ unsigned smem_u32(const void* p) {
    return (unsigned)__cvta_generic_to_shared(p);
}
__device__ __forceinline__ void cp16(unsigned dst, const void* src) {
    asm volatile("cp.async.cg.shared.global [%0], [%1], 16;" :: "r"(dst), "l"(src));
}
__device__ __forceinline__ void cp_commit() {
    asm volatile("cp.async.commit_group;");
}
template <int N>
__device__ __forceinline__ void cp_wait() {
    asm volatile("cp.async.wait_group %0;" :: "n"(N));
}

// ---------------------------------------------------------------------------
// prepass: pack x -> half2; transpose+pack weights -> [n][k/2]
// ---------------------------------------------------------------------------
__global__ void pack_x_kernel(const float* __restrict__ in,
                              unsigned* __restrict__ out, int n4)
{
    int i = blockIdx.x * blockDim.x + threadIdx.x;
    if (i < n4) {
        float4 v = ((const float4*)in)[i];
        out[2 * i]     = packh2(v.x, v.y);
        out[2 * i + 1] = packh2(v.z, v.w);
    }
}

__global__ __launch_bounds__(256) void transpack_kernel(
    const float* __restrict__ in, unsigned* __restrict__ out, int K, int N)
{
    __shared__ float t[64][33];
    int n0 = blockIdx.x * 32, k0 = blockIdx.y * 64;
#pragma unroll
    for (int i = 0; i < 8; ++i) {
        int idx = i * 256 + threadIdx.x;
        int r = idx >> 5, c = idx & 31;
        t[r][c] = in[(size_t)(k0 + r) * N + n0 + c];
    }
    __syncthreads();
#pragma unroll
    for (int i = 0; i < 4; ++i) {
        int idx = i * 256 + threadIdx.x;
        int nl = idx >> 5, j = idx & 31;
        out[(size_t)(n0 + nl) * (K / 2) + k0 / 2 + j] =
            packh2(t[2 * j][nl], t[2 * j + 1][nl]);
    }
}

// ---------------------------------------------------------------------------
// FP16 TC GEMM: C = A@B^T + bias. A[m][k-u32], B[n][k-u32] (half2-packed).
// Block 128x128, 8 warps, warp tile 64x32 (wm=warp&1, wn=warp>>1).
// K' tile = 32 u32 (64 halves), double-buffered cp.async. NT = KU/32.
// EPI==1: QKV scatter (Q/K d-packed; V key-pair transposed via shuffles).
// EPI==2: Cout f32 = acc + bias.
// ---------------------------------------------------------------------------
#define GSTR 36
#define GTILE (128 * GSTR)     // per operand per buffer (u32)

__device__ __forceinline__ void g_issue(
    const unsigned* __restrict__ A, const unsigned* __restrict__ B,
    unsigned* sh, int tid, int kt, int buf, int m0, int n0, int KU)
{
    unsigned* Ad = sh + buf * 2 * GTILE;
    unsigned* Bd = Ad + GTILE;
#pragma unroll
    for (int i = 0; i < 8; ++i) {
        int idx = i * 256 + tid;
        if (idx < 1024) {
            int r = idx >> 3, c = idx & 7;
            cp16(smem_u32(Ad + r * GSTR + c * 4),
                 A + (size_t)(m0 + r) * KU + kt * 32 + c * 4);
        } else {
            int j = idx - 1024;
            int r = j >> 3, c = j & 7;
            cp16(smem_u32(Bd + r * GSTR + c * 4),
                 B + (size_t)(n0 + r) * KU + kt * 32 + c * 4);
        }
    }
    cp_commit();
}

template <int EPI>
__global__ __launch_bounds__(256, 2) void hgemm_tc(
    const unsigned* __restrict__ A, const unsigned* __restrict__ B,
    const float* __restrict__ bias, float* __restrict__ Cout,
    int N, int KU)
{
    extern __shared__ unsigned sh[];

    const int tid  = threadIdx.x;
    const int warp = tid >> 5;
    const int lane = tid & 31;
    const int g    = lane >> 2;
    const int tg   = lane & 3;
    const int wm   = warp & 1;
    const int wn   = warp >> 1;
    const int m0   = blockIdx.y * 128;
    const int n0   = blockIdx.x * 128;

    float acc[4][4][4];
#pragma unroll
    for (int i = 0; i < 4; ++i)
#pragma unroll
        for (int j = 0; j < 4; ++j)
#pragma unroll
            for (int r = 0; r < 4; ++r) acc[i][j][r] = 0.0f;

    const int NT = KU >> 5;   // 8
    g_issue(A, B, sh, tid, 0, 0, m0, n0, KU);

    for (int kt = 0; kt < NT; ++kt) {
        if (kt + 1 < NT) {
            g_issue(A, B, sh, tid, kt + 1, (kt + 1) & 1, m0, n0, KU);
            cp_wait<1>();
        } else {
            cp_wait<0>();
        }
        __syncthreads();

        const unsigned* Ab = sh + (kt & 1) * 2 * GTILE;
        const unsigned* Bb = Ab + GTILE;
#pragma unroll
        for (int ks = 0; ks < 4; ++ks) {
            int kk = ks * 8;
            unsigned a[4][4], b[4][2];
#pragma unroll
            for (int mt = 0; mt < 4; ++mt) {
                int m = wm * 64 + mt * 16 + g;
                a[mt][0] = Ab[m * GSTR + kk + tg];
                a[mt][1] = Ab[(m + 8) * GSTR + kk + tg];
                a[mt][2] = Ab[m * GSTR + kk + tg + 4];
                a[mt][3] = Ab[(m + 8) * GSTR + kk + tg + 4];
            }
#pragma unroll
            for (int nt = 0; nt < 4; ++nt) {
                int n = wn * 32 + nt * 8 + g;
                b[nt][0] = Bb[n * GSTR + kk + tg];
                b[nt][1] = Bb[n * GSTR + kk + tg + 4];
            }
#pragma unroll
            for (int mt = 0; mt < 4; ++mt)
#pragma unroll
                for (int nt = 0; nt < 4; ++nt)
                    mma16(acc[mt][nt], a[mt][0], a[mt][1], a[mt][2], a[mt][3],
                          b[nt][0], b[nt][1]);
        }
        __syncthreads();
    }

    // ---- epilogue ----
    if (EPI == 1) {
#pragma unroll
        for (int mt = 0; mt < 4; ++mt) {
            int m  = m0 + wm * 64 + mt * 16 + g;
            int t  = m >> 10;
            int hw0 = m & 1023;
            int hw1 = (m + 8) & 1023;
#pragma unroll
            for (int nt = 0; nt < 4; ++nt) {
                int n   = n0 + wn * 32 + nt * 8 + 2 * tg;
                float2 bv = *(const float2*)(bias + n);
                int s   = n >> 9;           // warp-uniform
                int rem = n & 511;
                int h   = rem >> 6;
                int d   = rem & 63;         // even
                float v00 = acc[mt][nt][0] + bv.x;   // (hw0, d)
                float v01 = acc[mt][nt][1] + bv.y;   // (hw0, d+1)
                float v10 = acc[mt][nt][2] + bv.x;   // (hw1, d)
                float v11 = acc[mt][nt][3] + bv.y;   // (hw1, d+1)
                if (s == 0) {
                    size_t base = ((size_t)(h * 16 + t) * 1024) * HU + d / 2;
                    g_q[base + (size_t)hw0 * HU] = packh2(v00 * 0.125f, v01 * 0.125f);
                    g_q[base + (size_t)hw1 * HU] = packh2(v10 * 0.125f, v11 * 0.125f);
                } else if (s == 1) {
                    size_t base = ((size_t)(h * 16 + t) * 1024) * HU + d / 2;
                    g_k[base + (size_t)hw0 * HU] = packh2(v00, v01);
                    g_k[base + (size_t)hw1 * HU] = packh2(v10, v11);
                } else {
                    // V: transpose to [d][key-pair]; exchange with row-partner g^1
                    float p00 = __shfl_xor_sync(0xFFFFFFFFu, v00, 4);
                    float p01 = __shfl_xor_sync(0xFFFFFFFFu, v01, 4);
                    float p10 = __shfl_xor_sync(0xFFFFFFFFu, v10, 4);
                    float p11 = __shfl_xor_sync(0xFFFFFFFFu, v11, 4);
                    if ((g & 1) == 0) {   // even rows own the pair (hw, hw+1)
                        size_t base = ((size_t)(h * 16 + t) * 64 + d) * (HWDIM / 2);
                        size_t base1 = base + (HWDIM / 2);   // d+1
                        g_vt[base  + (hw0 >> 1)] = packh2(v00, p00);
                        g_vt[base1 + (hw0 >> 1)] = packh2(v01, p01);
                        g_vt[base  + (hw1 >> 1)] = packh2(v10, p10);
                        g_vt[base1 + (hw1 >> 1)] = packh2(v11, p11);
                    }
                }
            }
        }
    } else {
#pragma unroll
        for (int mt = 0; mt < 4; ++mt) {
            int m = m0 + wm * 64 + mt * 16 + g;
#pragma unroll
            for (int nt = 0; nt < 4; ++nt) {
                int n = n0 + wn * 32 + nt * 8 + 2 * tg;
                float2 bv = *(const float2*)(bias + n);
                float2 v0, v1;
                v0.x = acc[mt][nt][0] + bv.x;
                v0.y = acc[mt][nt][1] + bv.y;
                v1.x = acc[mt][nt][2] + bv.x;
                v1.y = acc[mt][nt][3] + bv.y;
                *(float2*)(Cout + (size_t)m * N + n)       = v0;
                *(float2*)(Cout + (size_t)(m + 8) * N + n) = v1;
            }
        }
    }
}

// ---------------------------------------------------------------------------
// FP16 flash attention. 256 thr / 8 warps; warp w owns q rows [w*16, w*16+16).
// K smem [64 key][36 u32 d-packed]; V smem [64 d][36 u32 key-packed].
// P goes straight from S registers into PV A-fragments (no shuffles/smem).
// ---------------------------------------------------------------------------
#define KVS 36
#define KVT (64 * KVS)

__device__ __forceinline__ void attn_issue(
    const unsigned* __restrict__ Kg, const unsigned* __restrict__ Vtg,
    unsigned* sm, int tid, int kt, int buf)
{
    unsigned* Kd = sm + buf * 2 * KVT;
    unsigned* Vd = Kd + KVT;
#pragma unroll
    for (int i = 0; i < 4; ++i) {
        int idx = i * 256 + tid;
        if (idx < 512) {
            int r = idx >> 3, c = idx & 7;
            cp16(smem_u32(Kd + r * KVS + c * 4),
                 Kg + (size_t)(kt * 64 + r) * HU + c * 4);
        } else {
            int j = idx - 512;
            int r = j >> 3, c = j & 7;
            cp16(smem_u32(Vd + r * KVS + c * 4),
                 Vtg + (size_t)r * (HWDIM / 2) + kt * 32 + c * 4);
        }
    }
    cp_commit();
}

__global__ __launch_bounds__(256, 2) void attn_kernel()
{
    extern __shared__ unsigned sm[];

    const int p  = blockIdx.y;
    const int q0 = blockIdx.x * 128;
    const unsigned* Qg  = g_q  + (size_t)p * HWDIM * HU;
    const unsigned* Kg  = g_k  + (size_t)p * HWDIM * HU;
    const unsigned* Vtg = g_vt + (size_t)p * HD * (HWDIM / 2);

    const int tid  = threadIdx.x;
    const int w    = tid >> 5;
    const int lane = tid & 31;
    const int g    = lane >> 2;
    const int tg   = lane & 3;
    const int m    = w * 16 + g;

    attn_issue(Kg, Vtg, sm, tid, 0, 0);

    // Q fragments (u32 half2): step s -> a0..a3
    unsigned Qr[4][4];
    {
        const unsigned* Q0 = Qg + (size_t)(q0 + m) * HU;
        const unsigned* Q1 = Q0 + 8 * HU;
#pragma unroll
        for (int s = 0; s < 4; ++s) {
            Qr[s][0] = __ldg(Q0 + s * 8 + tg);
            Qr[s][1] = __ldg(Q1 + s * 8 + tg);
            Qr[s][2] = __ldg(Q0 + s * 8 + tg + 4);
            Qr[s][3] = __ldg(Q1 + s * 8 + tg + 4);
        }
    }

    float O[8][4];
#pragma unroll
    for (int nt = 0; nt < 8; ++nt)
#pragma unroll
        for (int r = 0; r < 4; ++r) O[nt][r] = 0.0f;
    float mo[2] = {-1e30f, -1e30f};
    float l[2]  = {0.0f, 0.0f};

    for (int kt = 0; kt < 16; ++kt) {
        if (kt + 1 < 16) {
            attn_issue(Kg, Vtg, sm, tid, kt + 1, (kt + 1) & 1);
            cp_wait<1>();
        } else {
            cp_wait<0>();
        }
        __syncthreads();
        const unsigned* Kb = sm + (kt & 1) * 2 * KVT;
        const unsigned* Vb = Kb + KVT;

        // ---- S = Q K^T (Q pre-scaled 1/8) ----
        float S[8][4];
#pragma unroll
        for (int nk = 0; nk < 8; ++nk)
#pragma unroll
            for (int r = 0; r < 4; ++r) S[nk][r] = 0.0f;
#pragma unroll
        for (int ks = 0; ks < 4; ++ks) {
            int kk = ks * 8;
#pragma unroll
            for (int nk = 0; nk < 8; ++nk) {
                const unsigned* kr = Kb + (nk * 8 + g) * KVS + kk + tg;
                mma16(S[nk], Qr[ks][0], Qr[ks][1], Qr[ks][2], Qr[ks][3],
                      kr[0], kr[4]);
            }
        }

        // ---- online softmax (rows m, m+8) ----
        float mn[2] = {-1e30f, -1e30f};
#pragma unroll
        for (int nk = 0; nk < 8; ++nk) {
            mn[0] = fmaxf(mn[0], fmaxf(S[nk][0], S[nk][1]));
            mn[1] = fmaxf(mn[1], fmaxf(S[nk][2], S[nk][3]));
        }
#pragma unroll
        for (int s = 0; s < 2; ++s) {
            mn[s] = fmaxf(mn[s], __shfl_xor_sync(0xFFFFFFFFu, mn[s], 1));
            mn[s] = fmaxf(mn[s], __shfl_xor_sync(0xFFFFFFFFu, mn[s], 2));
            mn[s] = fmaxf(mn[s], mo[s]);
        }
        float al[2];
        al[0] = __expf(mo[0] - mn[0]);
        al[1] = __expf(mo[1] - mn[1]);
#pragma unroll
        for (int nt = 0; nt < 8; ++nt) {
            O[nt][0] *= al[0]; O[nt][1] *= al[0];
            O[nt][2] *= al[1]; O[nt][3] *= al[1];
        }
        float rs[2] = {0.0f, 0.0f};
#pragma unroll
        for (int nk = 0; nk < 8; ++nk) {
            float p0 = __expf(S[nk][0] - mn[0]);
            float p1 = __expf(S[nk][1] - mn[0]);
            float p2 = __expf(S[nk][2] - mn[1]);
            float p3 = __expf(S[nk][3] - mn[1]);
            rs[0] += p0 + p1;
            rs[1] += p2 + p3;
            S[nk][0] = p0; S[nk][1] = p1; S[nk][2] = p2; S[nk][3] = p3;
        }
#pragma unroll
        for (int s = 0; s < 2; ++s) {
            rs[s] += __shfl_xor_sync(0xFFFFFFFFu, rs[s], 1);
            rs[s] += __shfl_xor_sync(0xFFFFFFFFu, rs[s], 2);
            l[s] = l[s] * al[s] + rs[s];
            mo[s] = mn[s];
        }

        // ---- O += P V : P packs directly from S registers ----
#pragma unroll
        for (int ks = 0; ks < 4; ++ks) {
            unsigned a0 = packh2(S[2 * ks][0],     S[2 * ks][1]);
            unsigned a1 = packh2(S[2 * ks][2],     S[2 * ks][3]);
            unsigned a2 = packh2(S[2 * ks + 1][0], S[2 * ks + 1][1]);
            unsigned a3 = packh2(S[2 * ks + 1][2], S[2 * ks + 1][3]);
            int kk = ks * 8;
#pragma unroll
            for (int nt = 0; nt < 8; ++nt) {
                const unsigned* vr = Vb + (nt * 8 + g) * KVS + kk + tg;
                mma16(O[nt], a0, a1, a2, a3, vr[0], vr[4]);
            }
        }
        __syncthreads();
    }

    // ---- epilogue: normalize + pack + permuted store (half2) ----
    const int h = p >> 4;
    const int t = p & 15;
    {
        int q = q0 + m;
        float inv0 = 1.0f / l[0];
        float inv1 = 1.0f / l[1];
        size_t b0u = ((size_t)(h * 1024 + q) * 16 + t) * HU;
        size_t b1u = ((size_t)(h * 1024 + q + 8) * 16 + t) * HU;
#pragma unroll
        for (int nt = 0; nt < 8; ++nt) {
            int du = nt * 4 + tg;
            g_atth[b0u + du] = packh2(O[nt][0] * inv0, O[nt][1] * inv0);
            g_atth[b1u + du] = packh2(O[nt][2] * inv1, O[nt][3] * inv1);
        }
    }
}

// ---------------------------------------------------------------------------
extern "C" void kernel_launch(void* const* d_in, const int* in_sizes, int n_in,
                              void* d_out, int out_size)
{
    const float* x    = (const float*)d_in[0];
    const float* Wqkv = (const float*)d_in[1];
    const float* bqkv = (const float*)d_in[2];
    const float* Wout = (const float*)d_in[3];
    const float* bout = (const float*)d_in[4];
    float* out = (float*)d_out;

    unsigned *xh, *wqkvh, *wouth, *atth;
    cudaGetSymbolAddress((void**)&xh, g_xh);
    cudaGetSymbolAddress((void**)&wqkvh, g_wqkvh);
    cudaGetSymbolAddress((void**)&wouth, g_wouth);
    cudaGetSymbolAddress((void**)&atth, g_atth);

    // 0) prepass: pack x; transpose+pack weights
    pack_x_kernel<<<(M1 * CDIM / 4 + 255) / 256, 256>>>(x, xh, M1 * CDIM / 4);
    transpack_kernel<<<dim3(N1 / 32, CDIM / 64), 256>>>(Wqkv, wqkvh, CDIM, N1);
    transpack_kernel<<<dim3(CDIM / 32, CDIM / 64), 256>>>(Wout, wouth, CDIM, CDIM);

    const int gemm_smem = 2 * 2 * GTILE * (int)sizeof(unsigned);  // 73728
    cudaFuncSetAttribute(hgemm_tc<1>,
                         cudaFuncAttributeMaxDynamicSharedMemorySize, gemm_smem);
    cudaFuncSetAttribute(hgemm_tc<2>,
                         cudaFuncAttributeMaxDynamicSharedMemorySize, gemm_smem);

    // 1) QKV projection + scatter (Q/K d-packed, V key-pair transposed)
    hgemm_tc<1><<<dim3(N1 / 128, M1 / 128), 256, gemm_smem>>>(
        xh, wqkvh, bqkv, nullptr, N1, CU);

    // 2) flash attention
    const int attn_smem = 2 * 2 * KVT * (int)sizeof(unsigned);    // 36864
    cudaFuncSetAttribute(attn_kernel,
                         cudaFuncAttributeMaxDynamicSharedMemorySize, attn_smem);
    attn_kernel<<<dim3(HWDIM / 128, NPROB), 256, attn_smem>>>();

    // 3) output projection
    hgemm_tc<2><<<dim3(CDIM / 128, M1 / 128), 256, gemm_smem>>>(
        atth, wouth, bout, out, CDIM, CU);
}

// round 11
// speedup vs baseline: 2.0299x; 1.0597x over previous
#include <cuda_runtime.h>
#include <cuda_fp16.h>
#include <math.h>
#include <stdint.h>

// Problem constants
#define M1    16384     // B*T*HW rows
#define CDIM  512
#define N1    1536      // 3*C
#define NH    8
#define HD    64
#define TT    16
#define HWDIM 1024
#define NPROB 128       // NH * TT
#define CU    256       // CDIM/2 (u32 half2 units)
#define HU    32        // HD/2

// Scratch. All half2-packed u32, k-index pair-interleaved within 8-groups.
__device__ unsigned g_q[(size_t)NPROB * HWDIM * HU];      // [p][hw][il(d/2)], 1/8-scaled
__device__ unsigned g_k[(size_t)NPROB * HWDIM * HU];      // [p][key][il(d/2)]
__device__ unsigned g_vt[(size_t)NPROB * HD * (HWDIM/2)]; // [p][d][il(key/2)]
__device__ unsigned g_atth[(size_t)M1 * CU];              // [m][il(k/2)]
__device__ unsigned g_xh[(size_t)M1 * CU];                // [m][il(k/2)]
__device__ unsigned g_wqkvh[(size_t)N1 * CU];             // [n][il(k/2)]
__device__ unsigned g_wouth[(size_t)CDIM * CU];           // [n][il(k/2)]

// ---------------------------------------------------------------------------
// helpers
// ---------------------------------------------------------------------------
__device__ __forceinline__ unsigned packh2(float x, float y) {
    __half2 h = __floats2half2_rn(x, y);
    return *reinterpret_cast<unsigned*>(&h);
}

__device__ __forceinline__ void mma16(float c[4],
                                      unsigned a0, unsigned a1, unsigned a2,
                                      unsigned a3, unsigned b0, unsigned b1) {
    asm volatile(
        "mma.sync.aligned.m16n8k16.row.col.f32.f16.f16.f32 "
        "{%0,%1,%2,%3}, {%4,%5,%6,%7}, {%8,%9}, {%0,%1,%2,%3};\n"
        : "+f"(c[0]), "+f"(c[1]), "+f"(c[2]), "+f"(c[3])
        : "r"(a0), "r"(a1), "r"(a2), "r"(a3), "r"(b0), "r"(b1));
}

__device__ __forceinline__ unsigned smem_u32(const void* p) {
    return (unsigned)__cvta_generic_to_shared(p);
}
__device__ __forceinline__ void cp16(unsigned dst, const void* src) {
    asm volatile("cp.async.cg.shared.global [%0], [%1], 16;" :: "r"(dst), "l"(src));
}
__device__ __forceinline__ void cp_commit() {
    asm volatile("cp.async.commit_group;");
}
template <int N>
__device__ __forceinline__ void cp_wait() {
    asm volatile("cp.async.wait_group %0;" :: "n"(N));
}

// pair interleave within 8-u32 groups: (t, t+4) -> (2t, 2t+1)
__device__ __forceinline__ int perm8(int j) {
    return ((j & 3) << 1) | ((j >> 2) & 1);
}
__device__ __forceinline__ int IL(int u) {        // u32 k-index -> stored pos
    return (u & ~7) | perm8(u & 7);
}

// ---------------------------------------------------------------------------
// prepass: pack+interleave x; transpose+pack+interleave weights
// ---------------------------------------------------------------------------
__global__ void pack_x_kernel(const float* __restrict__ in,
                              unsigned* __restrict__ out, int n4)
{
    int i = blockIdx.x * blockDim.x + threadIdx.x;
    if (i < n4) {
        float4 v = ((const float4*)in)[i];
        int u0 = 2 * i, u1 = 2 * i + 1;    // rows are 256-u32 aligned
        out[IL(u0)] = packh2(v.x, v.y);
        out[IL(u1)] = packh2(v.z, v.w);
    }
}

__global__ __launch_bounds__(256) void transpack_kernel(
    const float* __restrict__ in, unsigned* __restrict__ out, int K, int N)
{
    __shared__ float t[64][33];
    int n0 = blockIdx.x * 32, k0 = blockIdx.y * 64;
#pragma unroll
    for (int i = 0; i < 8; ++i) {
        int idx = i * 256 + threadIdx.x;
        int r = idx >> 5, c = idx & 31;
        t[r][c] = in[(size_t)(k0 + r) * N + n0 + c];
    }
    __syncthreads();
#pragma unroll
    for (int i = 0; i < 4; ++i) {
        int idx = i * 256 + threadIdx.x;
        int nl = idx >> 5, j = idx & 31;     // j: u32 index within 64-col chunk
        out[(size_t)(n0 + nl) * (K / 2) + k0 / 2 + IL(j)] =
            packh2(t[2 * j][nl], t[2 * j + 1][nl]);
    }
}

// ---------------------------------------------------------------------------
// FP16 TC GEMM: C = A@B^T + bias. A[m][il k-u32], B[n][il k-u32].
// Block 128x128, 8 warps, warp tile 64x32. All fragment reads are LDS.64.
// smem stride 40 u32 (==8 mod 32 -> conflict-free pair loads).
// EPI==1: QKV scatter (interleaved targets); EPI==2: Cout f32.
// ---------------------------------------------------------------------------
#define GSTR 40
#define GTILE (128 * GSTR)     // per operand per buffer (u32)

__device__ __forceinline__ void g_issue(
    const unsigned* __restrict__ A, const unsigned* __restrict__ B,
    unsigned* sh, int tid, int kt, int buf, int m0, int n0, int KU)
{
    unsigned* Ad = sh + buf * 2 * GTILE;
    unsigned* Bd = Ad + GTILE;
#pragma unroll
    for (int i = 0; i < 8; ++i) {
        int idx = i * 256 + tid;
        if (idx < 1024) {
            int r = idx >> 3, c = idx & 7;
            cp16(smem_u32(Ad + r * GSTR + c * 4),
                 A + (size_t)(m0 + r) * KU + kt * 32 + c * 4);
        } else {
            int j = idx - 1024;
            int r = j >> 3, c = j & 7;
            cp16(smem_u32(Bd + r * GSTR + c * 4),
                 B + (size_t)(n0 + r) * KU + kt * 32 + c * 4);
        }
    }
    cp_commit();
}

template <int EPI>
__global__ __launch_bounds__(256, 2) void hgemm_tc(
    const unsigned* __restrict__ A, const unsigned* __restrict__ B,
    const float* __restrict__ bias, float* __restrict__ Cout,
    int N, int KU)
{
    extern __shared__ unsigned sh[];

    const int tid  = threadIdx.x;
    const int warp = tid >> 5;
    const int lane = tid & 31;
    const int g    = lane >> 2;
    const int tg   = lane & 3;
    const int wm   = warp & 1;
    const int wn   = warp >> 1;
    const int m0   = blockIdx.y * 128;
    const int n0   = blockIdx.x * 128;

    float acc[4][4][4];
#pragma unroll
    for (int i = 0; i < 4; ++i)
#pragma unroll
        for (int j = 0; j < 4; ++j)
#pragma unroll
            for (int r = 0; r < 4; ++r) acc[i][j][r] = 0.0f;

    const int NT = KU >> 5;   // 8
    g_issue(A, B, sh, tid, 0, 0, m0, n0, KU);

    for (int kt = 0; kt < NT; ++kt) {
        if (kt + 1 < NT) {
            g_issue(A, B, sh, tid, kt + 1, (kt + 1) & 1, m0, n0, KU);
            cp_wait<1>();
        } else {
            cp_wait<0>();
        }
        __syncthreads();

        const unsigned* Ab = sh + (kt & 1) * 2 * GTILE;
        const unsigned* Bb = Ab + GTILE;
#pragma unroll
        for (int ks = 0; ks < 4; ++ks) {
            int o = ks * 8 + 2 * tg;
            uint2 pa0[4], pa1[4], pb[4];
#pragma unroll
            for (int mt = 0; mt < 4; ++mt) {
                int m = wm * 64 + mt * 16 + g;
                pa0[mt] = *(const uint2*)(Ab + m * GSTR + o);
                pa1[mt] = *(const uint2*)(Ab + (m + 8) * GSTR + o);
            }
#pragma unroll
            for (int nt = 0; nt < 4; ++nt) {
                int n = wn * 32 + nt * 8 + g;
                pb[nt] = *(const uint2*)(Bb + n * GSTR + o);
            }
#pragma unroll
            for (int mt = 0; mt < 4; ++mt)
#pragma unroll
                for (int nt = 0; nt < 4; ++nt)
                    mma16(acc[mt][nt], pa0[mt].x, pa1[mt].x,
                          pa0[mt].y, pa1[mt].y, pb[nt].x, pb[nt].y);
        }
        __syncthreads();
    }

    // ---- epilogue ----
    if (EPI == 1) {
#pragma unroll
        for (int mt = 0; mt < 4; ++mt) {
            int m  = m0 + wm * 64 + mt * 16 + g;
            int t  = m >> 10;
            int hw0 = m & 1023;
            int hw1 = (m + 8) & 1023;
#pragma unroll
            for (int nt = 0; nt < 4; ++nt) {
                int n   = n0 + wn * 32 + nt * 8 + 2 * tg;
                float2 bv = *(const float2*)(bias + n);
                int s   = n >> 9;           // warp-uniform
                int rem = n & 511;
                int h   = rem >> 6;
                int d   = rem & 63;         // even
                int du  = IL(d >> 1);       // interleaved u32 pos
                float v00 = acc[mt][nt][0] + bv.x;   // (hw0, d)
                float v01 = acc[mt][nt][1] + bv.y;   // (hw0, d+1)
                float v10 = acc[mt][nt][2] + bv.x;   // (hw1, d)
                float v11 = acc[mt][nt][3] + bv.y;   // (hw1, d+1)
                if (s == 0) {
                    size_t base = ((size_t)(h * 16 + t) * 1024) * HU + du;
                    g_q[base + (size_t)hw0 * HU] = packh2(v00 * 0.125f, v01 * 0.125f);
                    g_q[base + (size_t)hw1 * HU] = packh2(v10 * 0.125f, v11 * 0.125f);
                } else if (s == 1) {
                    size_t base = ((size_t)(h * 16 + t) * 1024) * HU + du;
                    g_k[base + (size_t)hw0 * HU] = packh2(v00, v01);
                    g_k[base + (size_t)hw1 * HU] = packh2(v10, v11);
                } else {
                    // V: transpose to [d][il(key-pair)]; partner lane g^1 = row+1
                    float p00 = __shfl_xor_sync(0xFFFFFFFFu, v00, 4);
                    float p01 = __shfl_xor_sync(0xFFFFFFFFu, v01, 4);
                    float p10 = __shfl_xor_sync(0xFFFFFFFFu, v10, 4);
                    float p11 = __shfl_xor_sync(0xFFFFFFFFu, v11, 4);
                    if ((g & 1) == 0) {   // even rows own the pair (hw, hw+1)
                        size_t base  = ((size_t)(h * 16 + t) * 64 + d) * (HWDIM / 2);
                        size_t base1 = base + (HWDIM / 2);   // d+1
                        int c0 = IL(hw0 >> 1), c1 = IL(hw1 >> 1);
                        g_vt[base  + c0] = packh2(v00, p00);
                        g_vt[base1 + c0] = packh2(v01, p01);
                        g_vt[base  + c1] = packh2(v10, p10);
                        g_vt[base1 + c1] = packh2(v11, p11);
                    }
                }
            }
        }
    } else {
#pragma unroll
        for (int mt = 0; mt < 4; ++mt) {
            int m = m0 + wm * 64 + mt * 16 + g;
#pragma unroll
            for (int nt = 0; nt < 4; ++nt) {
                int n = n0 + wn * 32 + nt * 8 + 2 * tg;
                float2 bv = *(const float2*)(bias + n);
                float2 v0, v1;
                v0.x = acc[mt][nt][0] + bv.x;
                v0.y = acc[mt][nt][1] + bv.y;
                v1.x = acc[mt][nt][2] + bv.x;
                v1.y = acc[mt][nt][3] + bv.y;
                *(float2*)(Cout + (size_t)m * N + n)       = v0;
                *(float2*)(Cout + (size_t)(m + 8) * N + n) = v1;
            }
        }
    }
}

// ---------------------------------------------------------------------------
// FP16 flash attention. 256 thr / 8 warps; warp w owns q rows [w*16, w*16+16).
// K smem [64 key][il d-u32]; V smem [64 d][il key-u32]; stride 40 u32.
// All fragment reads LDS.64; P packs straight from S registers.
// ---------------------------------------------------------------------------
#define KVS 40
#define KVT (64 * KVS)

__device__ __forceinline__ void attn_issue(
    const unsigned* __restrict__ Kg, const unsigned* __restrict__ Vtg,
    unsigned* sm, int tid, int kt, int buf)
{
    unsigned* Kd = sm + buf * 2 * KVT;
    unsigned* Vd = Kd + KVT;
#pragma unroll
    for (int i = 0; i < 4; ++i) {
        int idx = i * 256 + tid;
        if (idx < 512) {
            int r = idx >> 3, c = idx & 7;
            cp16(smem_u32(Kd + r * KVS + c * 4),
                 Kg + (size_t)(kt * 64 + r) * HU + c * 4);
        } else {
            int j = idx - 512;
            int r = j >> 3, c = j & 7;
            cp16(smem_u32(Vd + r * KVS + c * 4),
                 Vtg + (size_t)r * (HWDIM / 2) + kt * 32 + c * 4);
        }
    }
    cp_commit();
}

__global__ __launch_bounds__(256, 2) void attn_kernel()
{
    extern __shared__ unsigned sm[];

    const int p  = blockIdx.y;
    const int q0 = blockIdx.x * 128;
    const unsigned* Qg  = g_q  + (size_t)p * HWDIM * HU;
    const unsigned* Kg  = g_k  + (size_t)p * HWDIM * HU;
    const unsigned* Vtg = g_vt + (size_t)p * HD * (HWDIM / 2);

    const int tid  = threadIdx.x;
    const int w    = tid >> 5;
    const int lane = tid & 31;
    const int g    = lane >> 2;
    const int tg   = lane & 3;
    const int m    = w * 16 + g;

    attn_issue(Kg, Vtg, sm, tid, 0, 0);

    // Q fragments (u32 half2, interleaved gmem): one uint2 per (s,row)
    unsigned Qr[4][4];
    {
        const unsigned* Q0 = Qg + (size_t)(q0 + m) * HU;
        const unsigned* Q1 = Q0 + 8 * HU;
#pragma unroll
        for (int s = 0; s < 4; ++s) {
            uint2 qa = __ldg((const uint2*)(Q0 + s * 8 + 2 * tg));
            uint2 qb = __ldg((const uint2*)(Q1 + s * 8 + 2 * tg));
            Qr[s][0] = qa.x; Qr[s][2] = qa.y;
            Qr[s][1] = qb.x; Qr[s][3] = qb.y;
        }
    }

    float O[8][4];
#pragma unroll
    for (int nt = 0; nt < 8; ++nt)
#pragma unroll
        for (int r = 0; r < 4; ++r) O[nt][r] = 0.0f;
    float mo[2] = {-1e30f, -1e30f};
    float l[2]  = {0.0f, 0.0f};

    for (int kt = 0; kt < 16; ++kt) {
        if (kt + 1 < 16) {
            attn_issue(Kg, Vtg, sm, tid, kt + 1, (kt + 1) & 1);
            cp_wait<1>();
        } else {
            cp_wait<0>();
        }
        __syncthreads();
        const unsigned* Kb = sm + (kt & 1) * 2 * KVT;
        const unsigned* Vb = Kb + KVT;

        // ---- S = Q K^T (Q pre-scaled 1/8) ----
        float S[8][4];
#pragma unroll
        for (int nk = 0; nk < 8; ++nk)
#pragma unroll
            for (int r = 0; r < 4; ++r) S[nk][r] = 0.0f;
#pragma unroll
        for (int ks = 0; ks < 4; ++ks) {
            int o = ks * 8 + 2 * tg;
#pragma unroll
            for (int nk = 0; nk < 8; ++nk) {
                uint2 bk = *(const uint2*)(Kb + (nk * 8 + g) * KVS + o);
                mma16(S[nk], Qr[ks][0], Qr[ks][1], Qr[ks][2], Qr[ks][3],
                      bk.x, bk.y);
            }
        }

        // ---- online softmax (rows m, m+8) ----
        float mn[2] = {-1e30f, -1e30f};
#pragma unroll
        for (int nk = 0; nk < 8; ++nk) {
            mn[0] = fmaxf(mn[0], fmaxf(S[nk][0], S[nk][1]));
            mn[1] = fmaxf(mn[1], fmaxf(S[nk][2], S[nk][3]));
        }
#pragma unroll
        for (int s = 0; s < 2; ++s) {
            mn[s] = fmaxf(mn[s], __shfl_xor_sync(0xFFFFFFFFu, mn[s], 1));
            mn[s] = fmaxf(mn[s], __shfl_xor_sync(0xFFFFFFFFu, mn[s], 2));
            mn[s] = fmaxf(mn[s], mo[s]);
        }
        float al[2];
        al[0] = __expf(mo[0] - mn[0]);
        al[1] = __expf(mo[1] - mn[1]);
#pragma unroll
        for (int nt = 0; nt < 8; ++nt) {
            O[nt][0] *= al[0]; O[nt][1] *= al[0];
            O[nt][2] *= al[1]; O[nt][3] *= al[1];
        }
        float rs[2] = {0.0f, 0.0f};
#pragma unroll
        for (int nk = 0; nk < 8; ++nk) {
            float p0 = __expf(S[nk][0] - mn[0]);
            float p1 = __expf(S[nk][1] - mn[0]);
            float p2 = __expf(S[nk][2] - mn[1]);
            float p3 = __expf(S[nk][3] - mn[1]);
            rs[0] += p0 + p1;
            rs[1] += p2 + p3;
            S[nk][0] = p0; S[nk][1] = p1; S[nk][2] = p2; S[nk][3] = p3;
        }
#pragma unroll
        for (int s = 0; s < 2; ++s) {
            rs[s] += __shfl_xor_sync(0xFFFFFFFFu, rs[s], 1);
            rs[s] += __shfl_xor_sync(0xFFFFFFFFu, rs[s], 2);
            l[s] = l[s] * al[s] + rs[s];
            mo[s] = mn[s];
        }

        // ---- O += P V : P packs directly from S registers ----
#pragma unroll
        for (int ks = 0; ks < 4; ++ks) {
            unsigned a0 = packh2(S[2 * ks][0],     S[2 * ks][1]);
            unsigned a1 = packh2(S[2 * ks][2],     S[2 * ks][3]);
            unsigned a2 = packh2(S[2 * ks + 1][0], S[2 * ks + 1][1]);
            unsigned a3 = packh2(S[2 * ks + 1][2], S[2 * ks + 1][3]);
            int o = ks * 8 + 2 * tg;
#pragma unroll
            for (int nt = 0; nt < 8; ++nt) {
                uint2 bv = *(const uint2*)(Vb + (nt * 8 + g) * KVS + o);
                mma16(O[nt], a0, a1, a2, a3, bv.x, bv.y);
            }
        }
        __syncthreads();
    }

    // ---- epilogue: normalize + pack + permuted interleaved store ----
    const int h = p >> 4;
    const int t = p & 15;
    {
        int q = q0 + m;
        float inv0 = 1.0f / l[0];
        float inv1 = 1.0f / l[1];
        size_t b0u = ((size_t)(h * 1024 + q) * 16 + t) * HU;
        size_t b1u = ((size_t)(h * 1024 + q + 8) * 16 + t) * HU;
#pragma unroll
        for (int nt = 0; nt < 8; ++nt) {
            int du = IL(nt * 4 + tg);
            g_atth[b0u + du] = packh2(O[nt][0] * inv0, O[nt][1] * inv0);
            g_atth[b1u + du] = packh2(O[nt][2] * inv1, O[nt][3] * inv1);
        }
    }
}

// ---------------------------------------------------------------------------
extern "C" void kernel_launch(void* const* d_in, const int* in_sizes, int n_in,
                              void* d_out, int out_size)
{
    const float* x    = (const float*)d_in[0];
    const float* Wqkv = (const float*)d_in[1];
    const float* bqkv = (const float*)d_in[2];
    const float* Wout = (const float*)d_in[3];
    const float* bout = (const float*)d_in[4];
    float* out = (float*)d_out;

    unsigned *xh, *wqkvh, *wouth, *atth;
    cudaGetSymbolAddress((void**)&xh, g_xh);
    cudaGetSymbolAddress((void**)&wqkvh, g_wqkvh);
    cudaGetSymbolAddress((void**)&wouth, g_wouth);
    cudaGetSymbolAddress((void**)&atth, g_atth);

    // 0) prepass: pack+interleave x; transpose+pack+interleave weights
    pack_x_kernel<<<(M1 * CDIM / 4 + 255) / 256, 256>>>(x, xh, M1 * CDIM / 4);
    transpack_kernel<<<dim3(N1 / 32, CDIM / 64), 256>>>(Wqkv, wqkvh, CDIM, N1);
    transpack_kernel<<<dim3(CDIM / 32, CDIM / 64), 256>>>(Wout, wouth, CDIM, CDIM);

    const int gemm_smem = 2 * 2 * GTILE * (int)sizeof(unsigned);  // 81920
    cudaFuncSetAttribute(hgemm_tc<1>,
                         cudaFuncAttributeMaxDynamicSharedMemorySize, gemm_smem);
    cudaFuncSetAttribute(hgemm_tc<2>,
                         cudaFuncAttributeMaxDynamicSharedMemorySize, gemm_smem);

    // 1) QKV projection + scatter
    hgemm_tc<1><<<dim3(N1 / 128, M1 / 128), 256, gemm_smem>>>(
        xh, wqkvh, bqkv, nullptr, N1, CU);

    // 2) flash attention
    const int attn_smem = 2 * 2 * KVT * (int)sizeof(unsigned);    // 40960
    cudaFuncSetAttribute(attn_kernel,
                         cudaFuncAttributeMaxDynamicSharedMemorySize, attn_smem);
    attn_kernel<<<dim3(HWDIM / 128, NPROB), 256, attn_smem>>>();

    // 3) output projection
    hgemm_tc<2><<<dim3(CDIM / 128, M1 / 128), 256, gemm_smem>>>(
        atth, wouth, bout, out, CDIM, CU);
}

// round 12
// speedup vs baseline: 2.1083x; 1.0386x over previous
#include <cuda_runtime.h>
#include <cuda_fp16.h>
#include <math.h>
#include <stdint.h>

// Problem constants
#define M1    16384     // B*T*HW rows
#define CDIM  512
#define N1    1536      // 3*C
#define NH    8
#define HD    64
#define TT    16
#define HWDIM 1024
#define NPROB 128       // NH * TT
#define CU    256       // CDIM/2 (u32 half2 units)
#define HU    32        // HD/2
#define KUC   256       // compile-time K (u32) for both GEMMs
#define LOG2E 1.4426950408889634f

// Scratch. All half2-packed u32, k-index pair-interleaved within 8-groups.
__device__ unsigned g_q[(size_t)NPROB * HWDIM * HU];      // [p][hw][il(d/2)], *log2e/8
__device__ unsigned g_k[(size_t)NPROB * HWDIM * HU];      // [p][key][il(d/2)]
__device__ unsigned g_vt[(size_t)NPROB * HD * (HWDIM/2)]; // [p][d][il(key/2)]
__device__ unsigned g_atth[(size_t)M1 * CU];              // [m][il(k/2)]
__device__ unsigned g_xh[(size_t)M1 * CU];                // [m][il(k/2)]
__device__ unsigned g_wqkvh[(size_t)N1 * CU];             // [n][il(k/2)]
__device__ unsigned g_wouth[(size_t)CDIM * CU];           // [n][il(k/2)]

// ---------------------------------------------------------------------------
// helpers
// ---------------------------------------------------------------------------
__device__ __forceinline__ unsigned packh2(float x, float y) {
    __half2 h = __floats2half2_rn(x, y);
    return *reinterpret_cast<unsigned*>(&h);
}

__device__ __forceinline__ void mma16(float c[4],
                                      unsigned a0, unsigned a1, unsigned a2,
                                      unsigned a3, unsigned b0, unsigned b1) {
    asm volatile(
        "mma.sync.aligned.m16n8k16.row.col.f32.f16.f16.f32 "
        "{%0,%1,%2,%3}, {%4,%5,%6,%7}, {%8,%9}, {%0,%1,%2,%3};\n"
        : "+f"(c[0]), "+f"(c[1]), "+f"(c[2]), "+f"(c[3])
        : "r"(a0), "r"(a1), "r"(a2), "r"(a3), "r"(b0), "r"(b1));
}

__device__ __forceinline__ unsigned smem_u32(const void* p) {
    return (unsigned)__cvta_generic_to_shared(p);
}
__device__ __forceinline__ void cp16(unsigned dst, const void* src) {
    asm volatile("cp.async.cg.shared.global [%0], [%1], 16;" :: "r"(dst), "l"(src));
}
__device__ __forceinline__ void cp_commit() {
    asm volatile("cp.async.commit_group;");
}
template <int N>
__device__ __forceinline__ void cp_wait() {
    asm volatile("cp.async.wait_group %0;" :: "n"(N));
}

// pair interleave within 8-u32 groups: (t, t+4) -> (2t, 2t+1)
__device__ __forceinline__ int perm8(int j) {
    return ((j & 3) << 1) | ((j >> 2) & 1);
}
__device__ __forceinline__ int IL(int u) {        // u32 k-index -> stored pos
    return (u & ~7) | perm8(u & 7);
}

// ---------------------------------------------------------------------------
// prepass: pack+interleave x; transpose+pack+interleave weights
// ---------------------------------------------------------------------------
__global__ void pack_x_kernel(const float* __restrict__ in,
                              unsigned* __restrict__ out, int n4)
{
    int i = blockIdx.x * blockDim.x + threadIdx.x;
    if (i < n4) {
        float4 v = ((const float4*)in)[i];
        int u0 = 2 * i, u1 = 2 * i + 1;    // rows are 256-u32 aligned
        out[IL(u0)] = packh2(v.x, v.y);
        out[IL(u1)] = packh2(v.z, v.w);
    }
}

__global__ __launch_bounds__(256) void transpack_kernel(
    const float* __restrict__ in, unsigned* __restrict__ out, int K, int N)
{
    __shared__ float t[64][33];
    int n0 = blockIdx.x * 32, k0 = blockIdx.y * 64;
#pragma unroll
    for (int i = 0; i < 8; ++i) {
        int idx = i * 256 + threadIdx.x;
        int r = idx >> 5, c = idx & 31;
        t[r][c] = in[(size_t)(k0 + r) * N + n0 + c];
    }
    __syncthreads();
#pragma unroll
    for (int i = 0; i < 4; ++i) {
        int idx = i * 256 + threadIdx.x;
        int nl = idx >> 5, j = idx & 31;
        out[(size_t)(n0 + nl) * (K / 2) + k0 / 2 + IL(j)] =
            packh2(t[2 * j][nl], t[2 * j + 1][nl]);
    }
}

// ---------------------------------------------------------------------------
// FP16 TC GEMM: C = A@B^T + bias. A[m][il k-u32], B[n][il k-u32], K=KUC.
// Block 128x128, 8 warps, warp tile 64x32, LDS.64 fragments (stride 40).
// 2-stage cp.async, ONE barrier per k-tile (wait -> sync -> issue -> compute).
// EPI==1: QKV scatter; EPI==2: Cout f32 = acc + bias.
// ---------------------------------------------------------------------------
#define GSTR 40
#define GTILE (128 * GSTR)     // per operand per buffer (u32)

__device__ __forceinline__ void g_issue(
    const unsigned* __restrict__ A, const unsigned* __restrict__ B,
    unsigned* sh, int tid, int kt, int buf, int m0, int n0)
{
    unsigned* Ad = sh + buf * 2 * GTILE;
    unsigned* Bd = Ad + GTILE;
#pragma unroll
    for (int i = 0; i < 8; ++i) {
        int idx = i * 256 + tid;
        if (idx < 1024) {
            int r = idx >> 3, c = idx & 7;
            cp16(smem_u32(Ad + r * GSTR + c * 4),
                 A + (size_t)(m0 + r) * KUC + kt * 32 + c * 4);
        } else {
            int j = idx - 1024;
            int r = j >> 3, c = j & 7;
            cp16(smem_u32(Bd + r * GSTR + c * 4),
                 B + (size_t)(n0 + r) * KUC + kt * 32 + c * 4);
        }
    }
    cp_commit();
}

template <int EPI>
__global__ __launch_bounds__(256, 2) void hgemm_tc(
    const unsigned* __restrict__ A, const unsigned* __restrict__ B,
    const float* __restrict__ bias, float* __restrict__ Cout, int N)
{
    extern __shared__ unsigned sh[];

    const int tid  = threadIdx.x;
    const int warp = tid >> 5;
    const int lane = tid & 31;
    const int g    = lane >> 2;
    const int tg   = lane & 3;
    const int wm   = warp & 1;
    const int wn   = warp >> 1;
    const int m0   = blockIdx.y * 128;
    const int n0   = blockIdx.x * 128;

    float acc[4][4][4];
#pragma unroll
    for (int i = 0; i < 4; ++i)
#pragma unroll
        for (int j = 0; j < 4; ++j)
#pragma unroll
            for (int r = 0; r < 4; ++r) acc[i][j][r] = 0.0f;

    const int NT = KUC >> 5;   // 8
    g_issue(A, B, sh, tid, 0, 0, m0, n0);

    for (int kt = 0; kt < NT; ++kt) {
        cp_wait<0>();          // only group kt in flight
        __syncthreads();       // all readers of buf (kt+1)&1 (iter kt-1) done
        if (kt + 1 < NT)
            g_issue(A, B, sh, tid, kt + 1, (kt + 1) & 1, m0, n0);

        const unsigned* Ab = sh + (kt & 1) * 2 * GTILE;
        const unsigned* Bb = Ab + GTILE;
#pragma unroll
        for (int ks = 0; ks < 4; ++ks) {
            int o = ks * 8 + 2 * tg;
            uint2 pa0[4], pa1[4], pb[4];
#pragma unroll
            for (int mt = 0; mt < 4; ++mt) {
                int m = wm * 64 + mt * 16 + g;
                pa0[mt] = *(const uint2*)(Ab + m * GSTR + o);
                pa1[mt] = *(const uint2*)(Ab + (m + 8) * GSTR + o);
            }
#pragma unroll
            for (int nt = 0; nt < 4; ++nt) {
                int n = wn * 32 + nt * 8 + g;
                pb[nt] = *(const uint2*)(Bb + n * GSTR + o);
            }
#pragma unroll
            for (int mt = 0; mt < 4; ++mt)
#pragma unroll
                for (int nt = 0; nt < 4; ++nt)
                    mma16(acc[mt][nt], pa0[mt].x, pa1[mt].x,
                          pa0[mt].y, pa1[mt].y, pb[nt].x, pb[nt].y);
        }
    }

    // ---- epilogue ----
    if (EPI == 1) {
#pragma unroll
        for (int mt = 0; mt < 4; ++mt) {
            int m  = m0 + wm * 64 + mt * 16 + g;
            int t  = m >> 10;
            int hw0 = m & 1023;
            int hw1 = (m + 8) & 1023;
#pragma unroll
            for (int nt = 0; nt < 4; ++nt) {
                int n   = n0 + wn * 32 + nt * 8 + 2 * tg;
                float2 bv = *(const float2*)(bias + n);
                int s   = n >> 9;           // warp-uniform
                int rem = n & 511;
                int h   = rem >> 6;
                int d   = rem & 63;         // even
                int du  = IL(d >> 1);       // interleaved u32 pos
                float v00 = acc[mt][nt][0] + bv.x;   // (hw0, d)
                float v01 = acc[mt][nt][1] + bv.y;   // (hw0, d+1)
                float v10 = acc[mt][nt][2] + bv.x;   // (hw1, d)
                float v11 = acc[mt][nt][3] + bv.y;   // (hw1, d+1)
                if (s == 0) {
                    const float qs = 0.125f * LOG2E;   // exp2-domain softmax
                    size_t base = ((size_t)(h * 16 + t) * 1024) * HU + du;
                    g_q[base + (size_t)hw0 * HU] = packh2(v00 * qs, v01 * qs);
                    g_q[base + (size_t)hw1 * HU] = packh2(v10 * qs, v11 * qs);
                } else if (s == 1) {
                    size_t base = ((size_t)(h * 16 + t) * 1024) * HU + du;
                    g_k[base + (size_t)hw0 * HU] = packh2(v00, v01);
                    g_k[base + (size_t)hw1 * HU] = packh2(v10, v11);
                } else {
                    // V: transpose to [d][il(key-pair)]; partner lane g^1 = row+1
                    float p00 = __shfl_xor_sync(0xFFFFFFFFu, v00, 4);
                    float p01 = __shfl_xor_sync(0xFFFFFFFFu, v01, 4);
                    float p10 = __shfl_xor_sync(0xFFFFFFFFu, v10, 4);
                    float p11 = __shfl_xor_sync(0xFFFFFFFFu, v11, 4);
                    if ((g & 1) == 0) {   // even rows own the pair (hw, hw+1)
                        size_t base  = ((size_t)(h * 16 + t) * 64 + d) * (HWDIM / 2);
                        size_t base1 = base + (HWDIM / 2);   // d+1
                        int c0 = IL(hw0 >> 1), c1 = IL(hw1 >> 1);
                        g_vt[base  + c0] = packh2(v00, p00);
                        g_vt[base1 + c0] = packh2(v01, p01);
                        g_vt[base  + c1] = packh2(v10, p10);
                        g_vt[base1 + c1] = packh2(v11, p11);
                    }
                }
            }
        }
    } else {
#pragma unroll
        for (int mt = 0; mt < 4; ++mt) {
            int m = m0 + wm * 64 + mt * 16 + g;
#pragma unroll
            for (int nt = 0; nt < 4; ++nt) {
                int n = n0 + wn * 32 + nt * 8 + 2 * tg;
                float2 bv = *(const float2*)(bias + n);
                float2 v0, v1;
                v0.x = acc[mt][nt][0] + bv.x;
                v0.y = acc[mt][nt][1] + bv.y;
                v1.x = acc[mt][nt][2] + bv.x;
                v1.y = acc[mt][nt][3] + bv.y;
                *(float2*)(Cout + (size_t)m * N + n)       = v0;
                *(float2*)(Cout + (size_t)(m + 8) * N + n) = v1;
            }
        }
    }
}

// ---------------------------------------------------------------------------
// FP16 flash attention, exp2-domain softmax (Q pre-scaled by log2e/8).
// 256 thr / 8 warps; warp w owns q rows [w*16, w*16+16).
// 3-stage cp.async ring, ONE barrier per KV tile.
// ---------------------------------------------------------------------------
#define KVS 40
#define KVT (64 * KVS)

__device__ __forceinline__ void attn_issue(
    const unsigned* __restrict__ Kg, const unsigned* __restrict__ Vtg,
    unsigned* sm, int tid, int kt, int buf)
{
    unsigned* Kd = sm + buf * 2 * KVT;
    unsigned* Vd = Kd + KVT;
#pragma unroll
    for (int i = 0; i < 4; ++i) {
        int idx = i * 256 + tid;
        if (idx < 512) {
            int r = idx >> 3, c = idx & 7;
            cp16(smem_u32(Kd + r * KVS + c * 4),
                 Kg + (size_t)(kt * 64 + r) * HU + c * 4);
        } else {
            int j = idx - 512;
            int r = j >> 3, c = j & 7;
            cp16(smem_u32(Vd + r * KVS + c * 4),
                 Vtg + (size_t)r * (HWDIM / 2) + kt * 32 + c * 4);
        }
    }
    cp_commit();
}

__global__ __launch_bounds__(256, 2) void attn_kernel()
{
    extern __shared__ unsigned sm[];

    const int p  = blockIdx.y;
    const int q0 = blockIdx.x * 128;
    const unsigned* Qg  = g_q  + (size_t)p * HWDIM * HU;
    const unsigned* Kg  = g_k  + (size_t)p * HWDIM * HU;
    const unsigned* Vtg = g_vt + (size_t)p * HD * (HWDIM / 2);

    const int tid  = threadIdx.x;
    const int w    = tid >> 5;
    const int lane = tid & 31;
    const int g    = lane >> 2;
    const int tg   = lane & 3;
    const int m    = w * 16 + g;

    attn_issue(Kg, Vtg, sm, tid, 0, 0);
    attn_issue(Kg, Vtg, sm, tid, 1, 1);

    // Q fragments (u32 half2, interleaved gmem): one uint2 per (s,row)
    unsigned Qr[4][4];
    {
        const unsigned* Q0 = Qg + (size_t)(q0 + m) * HU;
        const unsigned* Q1 = Q0 + 8 * HU;
#pragma unroll
        for (int s = 0; s < 4; ++s) {
            uint2 qa = __ldg((const uint2*)(Q0 + s * 8 + 2 * tg));
            uint2 qb = __ldg((const uint2*)(Q1 + s * 8 + 2 * tg));
            Qr[s][0] = qa.x; Qr[s][2] = qa.y;
            Qr[s][1] = qb.x; Qr[s][3] = qb.y;
        }
    }

    float O[8][4];
#pragma unroll
    for (int nt = 0; nt < 8; ++nt)
#pragma unroll
        for (int r = 0; r < 4; ++r) O[nt][r] = 0.0f;
    float mo[2] = {-1e30f, -1e30f};
    float l[2]  = {0.0f, 0.0f};

    int bc = 0;   // compute buffer = kt % 3
    int bi = 2;   // issue buffer  = (kt+2) % 3
    for (int kt = 0; kt < 16; ++kt) {
        if (kt + 1 < 16) cp_wait<1>(); else cp_wait<0>();   // group kt done
        __syncthreads();    // readers of buf bi (iter kt-1) all done
        if (kt + 2 < 16)
            attn_issue(Kg, Vtg, sm, tid, kt + 2, bi);

        const unsigned* Kb = sm + bc * 2 * KVT;
        const unsigned* Vb = Kb + KVT;

        // ---- S = Q K^T (log2-domain scores) ----
        float S[8][4];
#pragma unroll
        for (int nk = 0; nk < 8; ++nk)
#pragma unroll
            for (int r = 0; r < 4; ++r) S[nk][r] = 0.0f;
#pragma unroll
        for (int ks = 0; ks < 4; ++ks) {
            int o = ks * 8 + 2 * tg;
#pragma unroll
            for (int nk = 0; nk < 8; ++nk) {
                uint2 bk = *(const uint2*)(Kb + (nk * 8 + g) * KVS + o);
                mma16(S[nk], Qr[ks][0], Qr[ks][1], Qr[ks][2], Qr[ks][3],
                      bk.x, bk.y);
            }
        }

        // ---- online softmax (rows m, m+8), exp2 domain ----
        float mn[2] = {-1e30f, -1e30f};
#pragma unroll
        for (int nk = 0; nk < 8; ++nk) {
            mn[0] = fmaxf(mn[0], fmaxf(S[nk][0], S[nk][1]));
            mn[1] = fmaxf(mn[1], fmaxf(S[nk][2], S[nk][3]));
        }
#pragma unroll
        for (int s = 0; s < 2; ++s) {
            mn[s] = fmaxf(mn[s], __shfl_xor_sync(0xFFFFFFFFu, mn[s], 1));
            mn[s] = fmaxf(mn[s], __shfl_xor_sync(0xFFFFFFFFu, mn[s], 2));
            mn[s] = fmaxf(mn[s], mo[s]);
        }
        float al[2];
        al[0] = exp2f(mo[0] - mn[0]);
        al[1] = exp2f(mo[1] - mn[1]);
#pragma unroll
        for (int nt = 0; nt < 8; ++nt) {
            O[nt][0] *= al[0]; O[nt][1] *= al[0];
            O[nt][2] *= al[1]; O[nt][3] *= al[1];
        }
        float rs[2] = {0.0f, 0.0f};
#pragma unroll
        for (int nk = 0; nk < 8; ++nk) {
            float p0 = exp2f(S[nk][0] - mn[0]);
            float p1 = exp2f(S[nk][1] - mn[0]);
            float p2 = exp2f(S[nk][2] - mn[1]);
            float p3 = exp2f(S[nk][3] - mn[1]);
            rs[0] += p0 + p1;
            rs[1] += p2 + p3;
            S[nk][0] = p0; S[nk][1] = p1; S[nk][2] = p2; S[nk][3] = p3;
        }
#pragma unroll
        for (int s = 0; s < 2; ++s) {
            rs[s] += __shfl_xor_sync(0xFFFFFFFFu, rs[s], 1);
            rs[s] += __shfl_xor_sync(0xFFFFFFFFu, rs[s], 2);
            l[s] = l[s] * al[s] + rs[s];
            mo[s] = mn[s];
        }

        // ---- O += P V : P packs directly from S registers ----
#pragma unroll
        for (int ks = 0; ks < 4; ++ks) {
            unsigned a0 = packh2(S[2 * ks][0],     S[2 * ks][1]);
            unsigned a1 = packh2(S[2 * ks][2],     S[2 * ks][3]);
            unsigned a2 = packh2(S[2 * ks + 1][0], S[2 * ks + 1][1]);
            unsigned a3 = packh2(S[2 * ks + 1][2], S[2 * ks + 1][3]);
            int o = ks * 8 + 2 * tg;
#pragma unroll
            for (int nt = 0; nt < 8; ++nt) {
                uint2 bv = *(const uint2*)(Vb + (nt * 8 + g) * KVS + o);
                mma16(O[nt], a0, a1, a2, a3, bv.x, bv.y);
            }
        }

        bc = (bc == 2) ? 0 : bc + 1;
        bi = (bi == 2) ? 0 : bi + 1;
    }

    // ---- epilogue: normalize + pack + permuted interleaved store ----
    const int h = p >> 4;
    const int t = p & 15;
    {
        int q = q0 + m;
        float inv0 = 1.0f / l[0];
        float inv1 = 1.0f / l[1];
        size_t b0u = ((size_t)(h * 1024 + q) * 16 + t) * HU;
        size_t b1u = ((size_t)(h * 1024 + q + 8) * 16 + t) * HU;
#pragma unroll
        for (int nt = 0; nt < 8; ++nt) {
            int du = IL(nt * 4 + tg);
            g_atth[b0u + du] = packh2(O[nt][0] * inv0, O[nt][1] * inv0);
            g_atth[b1u + du] = packh2(O[nt][2] * inv1, O[nt][3] * inv1);
        }
    }
}

// ---------------------------------------------------------------------------
extern "C" void kernel_launch(void* const* d_in, const int* in_sizes, int n_in,
                              void* d_out, int out_size)
{
    const float* x    = (const float*)d_in[0];
    const float* Wqkv = (const float*)d_in[1];
    const float* bqkv = (const float*)d_in[2];
    const float* Wout = (const float*)d_in[3];
    const float* bout = (const float*)d_in[4];
    float* out = (float*)d_out;

    unsigned *xh, *wqkvh, *wouth, *atth;
    cudaGetSymbolAddress((void**)&xh, g_xh);
    cudaGetSymbolAddress((void**)&wqkvh, g_wqkvh);
    cudaGetSymbolAddress((void**)&wouth, g_wouth);
    cudaGetSymbolAddress((void**)&atth, g_atth);

    // 0) prepass: pack+interleave x; transpose+pack+interleave weights
    pack_x_kernel<<<(M1 * CDIM / 4 + 255) / 256, 256>>>(x, xh, M1 * CDIM / 4);
    transpack_kernel<<<dim3(N1 / 32, CDIM / 64), 256>>>(Wqkv, wqkvh, CDIM, N1);
    transpack_kernel<<<dim3(CDIM / 32, CDIM / 64), 256>>>(Wout, wouth, CDIM, CDIM);

    const int gemm_smem = 2 * 2 * GTILE * (int)sizeof(unsigned);  // 81920
    cudaFuncSetAttribute(hgemm_tc<1>,
                         cudaFuncAttributeMaxDynamicSharedMemorySize, gemm_smem);
    cudaFuncSetAttribute(hgemm_tc<2>,
                         cudaFuncAttributeMaxDynamicSharedMemorySize, gemm_smem);

    // 1) QKV projection + scatter
    hgemm_tc<1><<<dim3(N1 / 128, M1 / 128), 256, gemm_smem>>>(
        xh, wqkvh, bqkv, nullptr, N1);

    // 2) flash attention (3-stage ring)
    const int attn_smem = 3 * 2 * KVT * (int)sizeof(unsigned);    // 61440
    cudaFuncSetAttribute(attn_kernel,
                         cudaFuncAttributeMaxDynamicSharedMemorySize, attn_smem);
    attn_kernel<<<dim3(HWDIM / 128, NPROB), 256, attn_smem>>>();

    // 3) output projection
    hgemm_tc<2><<<dim3(CDIM / 128, M1 / 128), 256, gemm_smem>>>(
        atth, wouth, bout, out, CDIM);
}

// round 15
// speedup vs baseline: 2.2860x; 1.0843x over previous
#include <cuda_runtime.h>
#include <cuda_fp16.h>
#include <math.h>
#include <stdint.h>

// Problem constants
#define M1    16384     // B*T*HW rows
#define CDIM  512
#define N1    1536      // 3*C
#define NH    8
#define HD    64
#define TT    16
#define HWDIM 1024
#define NPROB 128       // NH * TT
#define CU    256       // CDIM/2 (u32 half2 units)
#define HU    32        // HD/2
#define LOG2E 1.4426950408889634f

// Scratch. half2-packed u32.
// Q/K/Vt: R12 pair-interleaved layouts. GEMM operands: fragment-quad layouts.
__device__ unsigned g_q[(size_t)NPROB * HWDIM * HU];      // [p][hw][il(d/2)], *log2e/8
__device__ unsigned g_k[(size_t)NPROB * HWDIM * HU];      // [p][key][il(d/2)]
__device__ unsigned g_vt[(size_t)NPROB * HD * (HWDIM/2)]; // [p][d][il(key/2)]
__device__ unsigned g_atth[(size_t)M1 * CU];              // quad-A
__device__ unsigned g_xh[(size_t)M1 * CU];                // quad-A
__device__ unsigned g_wqkvh[(size_t)N1 * CU];             // quad-B
__device__ unsigned g_wouth[(size_t)CDIM * CU];           // quad-B

// ---------------------------------------------------------------------------
// helpers
// ---------------------------------------------------------------------------
__device__ __forceinline__ unsigned packh2(float x, float y) {
    __half2 h = __floats2half2_rn(x, y);
    return *reinterpret_cast<unsigned*>(&h);
}

__device__ __forceinline__ void mma16(float c[4],
                                      unsigned a0, unsigned a1, unsigned a2,
                                      unsigned a3, unsigned b0, unsigned b1) {
    asm volatile(
        "mma.sync.aligned.m16n8k16.row.col.f32.f16.f16.f32 "
        "{%0,%1,%2,%3}, {%4,%5,%6,%7}, {%8,%9}, {%0,%1,%2,%3};\n"
        : "+f"(c[0]), "+f"(c[1]), "+f"(c[2]), "+f"(c[3])
        : "r"(a0), "r"(a1), "r"(a2), "r"(a3), "r"(b0), "r"(b1));
}

__device__ __forceinline__ unsigned smem_u32(const void* p) {
    return (unsigned)__cvta_generic_to_shared(p);
}
__device__ __forceinline__ void cp16(unsigned dst, const void* src) {
    asm volatile("cp.async.cg.shared.global [%0], [%1], 16;" :: "r"(dst), "l"(src));
}
__device__ __forceinline__ void cp_commit() {
    asm volatile("cp.async.commit_group;");
}
template <int N>
__device__ __forceinline__ void cp_wait() {
    asm volatile("cp.async.wait_group %0;" :: "n"(N));
}

// pair interleave: (t, t+4) -> (2t, 2t+1)
__device__ __forceinline__ int perm8(int j) {
    return ((j & 3) << 1) | ((j >> 2) & 1);
}
__device__ __forceinline__ int IL(int u) {
    return (u & ~7) | perm8(u & 7);
}

// ---- fragment-quad index functions (GEMM gmem layouts only) ----
// A quad: {A[m][k0], A[m+8][k0], A[m][k0+4], A[m+8][k0+4]}
__device__ __forceinline__ int quadA_idx(int m, int ku) {
    int mb = m >> 7, ml = m & 127;
    int mt = ml >> 4, rh = (ml >> 3) & 1, gg = ml & 7;
    int kt = ku >> 5, kl = ku & 31;
    int ks = kl >> 3, rem = kl & 7;
    int kh = rem >> 2, tg = rem & 3;
    int q = ((ks * 4 + tg) * 8 + mt) * 8 + ((gg + 2 * tg) & 7);
    return (mb * 8 + kt) * 4096 + q * 4 + (rh + 2 * kh);
}
// B quad: {B[n][k0], B[n][k0+4], B[n+8][k0], B[n+8][k0+4]}
__device__ __forceinline__ int quadB_idx(int n, int ku) {
    int nb = n >> 7, nl = n & 127;
    int wn = nl >> 5, r = nl & 31;
    int j = r >> 4, rr = r & 15;
    int nh = (rr >> 3) & 1, gg = rr & 7;
    int kt = ku >> 5, kl = ku & 31;
    int ks = kl >> 3, rem = kl & 7;
    int kh = rem >> 2, tg = rem & 3;
    int q = ((ks * 4 + tg) * 8 + wn * 2 + j) * 8 + ((gg + 2 * tg) & 7);
    return (nb * 8 + kt) * 4096 + q * 4 + (nh * 2 + kh);
}

// ---------------------------------------------------------------------------
// prepass: pack x -> quad-A; transpose+pack weights -> quad-B
// ---------------------------------------------------------------------------
__global__ void pack_x_kernel(const float* __restrict__ in,
                              unsigned* __restrict__ out, int n4)
{
    int i = blockIdx.x * blockDim.x + threadIdx.x;
    if (i < n4) {
        float4 v = ((const float4*)in)[i];
        int m = i >> 7;                 // 128 float4 per 512-float row
        int ku0 = (2 * i) & 255;
        out[quadA_idx(m, ku0)]     = packh2(v.x, v.y);
        out[quadA_idx(m, ku0 + 1)] = packh2(v.z, v.w);
    }
}

__global__ __launch_bounds__(256) void transpack_kernel(
    const float* __restrict__ in, unsigned* __restrict__ out, int K, int N)
{
    __shared__ float t[64][33];
    int n0 = blockIdx.x * 32, k0 = blockIdx.y * 64;
#pragma unroll
    for (int i = 0; i < 8; ++i) {
        int idx = i * 256 + threadIdx.x;
        int r = idx >> 5, c = idx & 31;
        t[r][c] = in[(size_t)(k0 + r) * N + n0 + c];
    }
    __syncthreads();
#pragma unroll
    for (int i = 0; i < 4; ++i) {
        int idx = i * 256 + threadIdx.x;
        int nl = idx >> 5, j = idx & 31;
        out[quadB_idx(n0 + nl, (k0 >> 1) + j)] =
            packh2(t[2 * j][nl], t[2 * j + 1][nl]);
    }
}

// ---------------------------------------------------------------------------
// FP16 TC GEMM, quad layouts, LDS.128 fragments. K = 256 u32 fixed.
// Block 128x128, 8 warps, warp tile 64x32. 2-stage, single barrier/k-tile.
// EPI==1: QKV scatter (Q/K/V in R12 pair-interleave layouts);
// EPI==2: Cout f32 = acc + bias.
// ---------------------------------------------------------------------------
__device__ __forceinline__ void g_issue(
    const unsigned* __restrict__ A, const unsigned* __restrict__ B,
    unsigned* sh, int tid, int kt, int buf, int mb, int nb)
{
    unsigned* Ad = sh + buf * 8192;
    unsigned* Bd = Ad + 4096;
    const unsigned* Ac = A + (size_t)(mb * 8 + kt) * 4096;
    const unsigned* Bc = B + (size_t)(nb * 8 + kt) * 4096;
#pragma unroll
    for (int i = 0; i < 8; ++i) {
        int idx = i * 256 + tid;
        if (idx < 1024) cp16(smem_u32(Ad + idx * 4), Ac + idx * 4);
        else            cp16(smem_u32(Bd + (idx - 1024) * 4), Bc + (idx - 1024) * 4);
    }
    cp_commit();
}

template <int EPI>
__global__ __launch_bounds__(256, 2) void hgemm_tc(
    const unsigned* __restrict__ A, const unsigned* __restrict__ B,
    const float* __restrict__ bias, float* __restrict__ Cout, int N)
{
    extern __shared__ unsigned sh[];

    const int tid  = threadIdx.x;
    const int warp = tid >> 5;
    const int lane = tid & 31;
    const int g    = lane >> 2;
    const int tg   = lane & 3;
    const int wm   = warp & 1;
    const int wn   = warp >> 1;
    const int mb   = blockIdx.y;
    const int nb   = blockIdx.x;
    const int swz  = (g + 2 * tg) & 7;

    float acc[4][4][4];
#pragma unroll
    for (int i = 0; i < 4; ++i)
#pragma unroll
        for (int j = 0; j < 4; ++j)
#pragma unroll
            for (int r = 0; r < 4; ++r) acc[i][j][r] = 0.0f;

    g_issue(A, B, sh, tid, 0, 0, mb, nb);

#pragma unroll
    for (int kt = 0; kt < 8; ++kt) {
        cp_wait<0>();
        __syncthreads();
        if (kt + 1 < 8)
            g_issue(A, B, sh, tid, kt + 1, (kt + 1) & 1, mb, nb);

        const unsigned* Ab = sh + (kt & 1) * 8192;
        const unsigned* Bb = Ab + 4096;
#pragma unroll
        for (int ks = 0; ks < 4; ++ks) {
            int bk = ks * 4 + tg;
            uint4 qa[4], qb[2];
#pragma unroll
            for (int mt = 0; mt < 4; ++mt)
                qa[mt] = *(const uint4*)(Ab + ((bk * 8 + wm * 4 + mt) * 8 + swz) * 4);
#pragma unroll
            for (int j = 0; j < 2; ++j)
                qb[j] = *(const uint4*)(Bb + ((bk * 8 + wn * 2 + j) * 8 + swz) * 4);
#pragma unroll
            for (int mt = 0; mt < 4; ++mt)
#pragma unroll
                for (int j = 0; j < 2; ++j) {
                    mma16(acc[mt][2 * j],     qa[mt].x, qa[mt].y, qa[mt].z, qa[mt].w,
                          qb[j].x, qb[j].y);
                    mma16(acc[mt][2 * j + 1], qa[mt].x, qa[mt].y, qa[mt].z, qa[mt].w,
                          qb[j].z, qb[j].w);
                }
        }
    }

    // ---- epilogue ----
    if (EPI == 1) {
#pragma unroll
        for (int mt = 0; mt < 4; ++mt) {
            int m  = mb * 128 + wm * 64 + mt * 16 + g;
            int t  = m >> 10;
            int hw0 = m & 1023;
            int hw1 = (m + 8) & 1023;
#pragma unroll
            for (int nt = 0; nt < 4; ++nt) {
                int n   = nb * 128 + wn * 32 + nt * 8 + 2 * tg;
                float2 bv = *(const float2*)(bias + n);
                int s   = n >> 9;           // warp-uniform
                int rem = n & 511;
                int h   = rem >> 6;
                int d   = rem & 63;         // even
                int du  = IL(d >> 1);       // interleaved u32 pos
                float v00 = acc[mt][nt][0] + bv.x;   // (hw0, d)
                float v01 = acc[mt][nt][1] + bv.y;   // (hw0, d+1)
                float v10 = acc[mt][nt][2] + bv.x;   // (hw1, d)
                float v11 = acc[mt][nt][3] + bv.y;   // (hw1, d+1)
                int p = h * 16 + t;
                if (s == 0) {
                    const float qs = 0.125f * LOG2E;   // exp2-domain softmax
                    size_t base = (size_t)p * 1024 * HU + du;
                    g_q[base + (size_t)hw0 * HU] = packh2(v00 * qs, v01 * qs);
                    g_q[base + (size_t)hw1 * HU] = packh2(v10 * qs, v11 * qs);
                } else if (s == 1) {
                    size_t base = (size_t)p * 1024 * HU + du;
                    g_k[base + (size_t)hw0 * HU] = packh2(v00, v01);
                    g_k[base + (size_t)hw1 * HU] = packh2(v10, v11);
                } else {
                    // V: transpose to [d][il(key-pair)]; partner lane g^1 = row+1
                    float p00 = __shfl_xor_sync(0xFFFFFFFFu, v00, 4);
                    float p01 = __shfl_xor_sync(0xFFFFFFFFu, v01, 4);
                    float p10 = __shfl_xor_sync(0xFFFFFFFFu, v10, 4);
                    float p11 = __shfl_xor_sync(0xFFFFFFFFu, v11, 4);
                    if ((g & 1) == 0) {   // even rows own the pair (hw, hw+1)
                        size_t base  = ((size_t)p * 64 + d) * (HWDIM / 2);
                        size_t base1 = base + (HWDIM / 2);   // d+1
                        int c0 = IL(hw0 >> 1), c1 = IL(hw1 >> 1);
                        g_vt[base  + c0] = packh2(v00, p00);
                        g_vt[base1 + c0] = packh2(v01, p01);
                        g_vt[base  + c1] = packh2(v10, p10);
                        g_vt[base1 + c1] = packh2(v11, p11);
                    }
                }
            }
        }
    } else {
#pragma unroll
        for (int mt = 0; mt < 4; ++mt) {
            int m = mb * 128 + wm * 64 + mt * 16 + g;
#pragma unroll
            for (int nt = 0; nt < 4; ++nt) {
                int n = nb * 128 + wn * 32 + nt * 8 + 2 * tg;
                float2 bv = *(const float2*)(bias + n);
                float2 v0, v1;
                v0.x = acc[mt][nt][0] + bv.x;
                v0.y = acc[mt][nt][1] + bv.y;
                v1.x = acc[mt][nt][2] + bv.x;
                v1.y = acc[mt][nt][3] + bv.y;
                *(float2*)(Cout + (size_t)m * N + n)       = v0;
                *(float2*)(Cout + (size_t)(m + 8) * N + n) = v1;
            }
        }
    }
}

// ---------------------------------------------------------------------------
// FP16 flash attention — R12-proven kernel (pair-interleaved K/V, exp2
// softmax, 3-stage ring, one barrier per KV tile). g_atth epilogue writes
// quad-A with the CORRECT row/ku decomposition:
//   row = (h*1024+q)*2 + (t>>3);  ku = (t&7)*32 + uu   (uu = nt*4+tg)
// ---------------------------------------------------------------------------
#define KVS 40
#define KVT (64 * KVS)

__device__ __forceinline__ void attn_issue(
    const unsigned* __restrict__ Kg, const unsigned* __restrict__ Vtg,
    unsigned* sm, int tid, int kt, int buf)
{
    unsigned* Kd = sm + buf * 2 * KVT;
    unsigned* Vd = Kd + KVT;
#pragma unroll
    for (int i = 0; i < 4; ++i) {
        int idx = i * 256 + tid;
        if (idx < 512) {
            int r = idx >> 3, c = idx & 7;
            cp16(smem_u32(Kd + r * KVS + c * 4),
                 Kg + (size_t)(kt * 64 + r) * HU + c * 4);
        } else {
            int j = idx - 512;
            int r = j >> 3, c = j & 7;
            cp16(smem_u32(Vd + r * KVS + c * 4),
                 Vtg + (size_t)r * (HWDIM / 2) + kt * 32 + c * 4);
        }
    }
    cp_commit();
}

__global__ __launch_bounds__(256, 2) void attn_kernel()
{
    extern __shared__ unsigned sm[];

    const int p  = blockIdx.y;
    const int q0 = blockIdx.x * 128;
    const unsigned* Qg  = g_q  + (size_t)p * HWDIM * HU;
    const unsigned* Kg  = g_k  + (size_t)p * HWDIM * HU;
    const unsigned* Vtg = g_vt + (size_t)p * HD * (HWDIM / 2);

    const int tid  = threadIdx.x;
    const int w    = tid >> 5;
    const int lane = tid & 31;
    const int g    = lane >> 2;
    const int tg   = lane & 3;
    const int m    = w * 16 + g;

    attn_issue(Kg, Vtg, sm, tid, 0, 0);
    attn_issue(Kg, Vtg, sm, tid, 1, 1);

    // Q fragments (pair-interleaved gmem): one uint2 per (s,row)
    unsigned Qr[4][4];
    {
        const unsigned* Q0 = Qg + (size_t)(q0 + m) * HU;
        const unsigned* Q1 = Q0 + 8 * HU;
#pragma unroll
        for (int s = 0; s < 4; ++s) {
            uint2 qa = __ldg((const uint2*)(Q0 + s * 8 + 2 * tg));
            uint2 qb = __ldg((const uint2*)(Q1 + s * 8 + 2 * tg));
            Qr[s][0] = qa.x; Qr[s][2] = qa.y;
            Qr[s][1] = qb.x; Qr[s][3] = qb.y;
        }
    }

    float O[8][4];
#pragma unroll
    for (int nt = 0; nt < 8; ++nt)
#pragma unroll
        for (int r = 0; r < 4; ++r) O[nt][r] = 0.0f;
    float mo[2] = {-1e30f, -1e30f};
    float l[2]  = {0.0f, 0.0f};

    int bc = 0;   // compute buffer
    int bi = 2;   // issue buffer
    for (int kt = 0; kt < 16; ++kt) {
        if (kt + 1 < 16) cp_wait<1>(); else cp_wait<0>();
        __syncthreads();
        if (kt + 2 < 16)
            attn_issue(Kg, Vtg, sm, tid, kt + 2, bi);

        const unsigned* Kb = sm + bc * 2 * KVT;
        const unsigned* Vb = Kb + KVT;

        // ---- S = Q K^T (log2-domain scores) ----
        float S[8][4];
#pragma unroll
        for (int nk = 0; nk < 8; ++nk)
#pragma unroll
            for (int r = 0; r < 4; ++r) S[nk][r] = 0.0f;
#pragma unroll
        for (int ks = 0; ks < 4; ++ks) {
            int o = ks * 8 + 2 * tg;
#pragma unroll
            for (int nk = 0; nk < 8; ++nk) {
                uint2 bk = *(const uint2*)(Kb + (nk * 8 + g) * KVS + o);
                mma16(S[nk], Qr[ks][0], Qr[ks][1], Qr[ks][2], Qr[ks][3],
                      bk.x, bk.y);
            }
        }

        // ---- online softmax (rows m, m+8), exp2 domain ----
        float mn[2] = {-1e30f, -1e30f};
#pragma unroll
        for (int nk = 0; nk < 8; ++nk) {
            mn[0] = fmaxf(mn[0], fmaxf(S[nk][0], S[nk][1]));
            mn[1] = fmaxf(mn[1], fmaxf(S[nk][2], S[nk][3]));
        }
#pragma unroll
        for (int s = 0; s < 2; ++s) {
            mn[s] = fmaxf(mn[s], __shfl_xor_sync(0xFFFFFFFFu, mn[s], 1));
            mn[s] = fmaxf(mn[s], __shfl_xor_sync(0xFFFFFFFFu, mn[s], 2));
            mn[s] = fmaxf(mn[s], mo[s]);
        }
        float al[2];
        al[0] = exp2f(mo[0] - mn[0]);
        al[1] = exp2f(mo[1] - mn[1]);
#pragma unroll
        for (int nt = 0; nt < 8; ++nt) {
            O[nt][0] *= al[0]; O[nt][1] *= al[0];
            O[nt][2] *= al[1]; O[nt][3] *= al[1];
        }
        float rs[2] = {0.0f, 0.0f};
#pragma unroll
        for (int nk = 0; nk < 8; ++nk) {
            float p0 = exp2f(S[nk][0] - mn[0]);
            float p1 = exp2f(S[nk][1] - mn[0]);
            float p2 = exp2f(S[nk][2] - mn[1]);
            float p3 = exp2f(S[nk][3] - mn[1]);
            rs[0] += p0 + p1;
            rs[1] += p2 + p3;
            S[nk][0] = p0; S[nk][1] = p1; S[nk][2] = p2; S[nk][3] = p3;
        }
#pragma unroll
        for (int s = 0; s < 2; ++s) {
            rs[s] += __shfl_xor_sync(0xFFFFFFFFu, rs[s], 1);
            rs[s] += __shfl_xor_sync(0xFFFFFFFFu, rs[s], 2);
            l[s] = l[s] * al[s] + rs[s];
            mo[s] = mn[s];
        }

        // ---- O += P V : P packs directly from S registers ----
#pragma unroll
        for (int ks = 0; ks < 4; ++ks) {
            unsigned a0 = packh2(S[2 * ks][0],     S[2 * ks][1]);
            unsigned a1 = packh2(S[2 * ks][2],     S[2 * ks][3]);
            unsigned a2 = packh2(S[2 * ks + 1][0], S[2 * ks + 1][1]);
            unsigned a3 = packh2(S[2 * ks + 1][2], S[2 * ks + 1][3]);
            int o = ks * 8 + 2 * tg;
#pragma unroll
            for (int nt = 0; nt < 8; ++nt) {
                uint2 bv = *(const uint2*)(Vb + (nt * 8 + g) * KVS + o);
                mma16(O[nt], a0, a1, a2, a3, bv.x, bv.y);
            }
        }

        bc = (bc == 2) ? 0 : bc + 1;
        bi = (bi == 2) ? 0 : bi + 1;
    }

    // ---- epilogue: normalize + pack + quad-A store (correct row/ku) ----
    const int h = p >> 4;
    const int t = p & 15;
    {
        int q = q0 + m;
        float inv0 = 1.0f / l[0];
        float inv1 = 1.0f / l[1];
        int row0 = (h * 1024 + q)     * 2 + (t >> 3);
        int row1 = (h * 1024 + q + 8) * 2 + (t >> 3);
        int kub  = (t & 7) * 32;
#pragma unroll
        for (int nt = 0; nt < 8; ++nt) {
            int ku = kub + nt * 4 + tg;
            g_atth[quadA_idx(row0, ku)] = packh2(O[nt][0] * inv0, O[nt][1] * inv0);
            g_atth[quadA_idx(row1, ku)] = packh2(O[nt][2] * inv1, O[nt][3] * inv1);
        }
    }
}

// ---------------------------------------------------------------------------
extern "C" void kernel_launch(void* const* d_in, const int* in_sizes, int n_in,
                              void* d_out, int out_size)
{
    const float* x    = (const float*)d_in[0];
    const float* Wqkv = (const float*)d_in[1];
    const float* bqkv = (const float*)d_in[2];
    const float* Wout = (const float*)d_in[3];
    const float* bout = (const float*)d_in[4];
    float* out = (float*)d_out;

    unsigned *xh, *wqkvh, *wouth, *atth;
    cudaGetSymbolAddress((void**)&xh, g_xh);
    cudaGetSymbolAddress((void**)&wqkvh, g_wqkvh);
    cudaGetSymbolAddress((void**)&wouth, g_wouth);
    cudaGetSymbolAddress((void**)&atth, g_atth);

    // 0) prepass: pack x -> quad-A; transpose+pack weights -> quad-B
    pack_x_kernel<<<(M1 * CDIM / 4 + 255) / 256, 256>>>(x, xh, M1 * CDIM / 4);
    transpack_kernel<<<dim3(N1 / 32, CDIM / 64), 256>>>(Wqkv, wqkvh, CDIM, N1);
    transpack_kernel<<<dim3(CDIM / 32, CDIM / 64), 256>>>(Wout, wouth, CDIM, CDIM);

    const int gemm_smem = 2 * 8192 * (int)sizeof(unsigned);   // 65536
    cudaFuncSetAttribute(hgemm_tc<1>,
                         cudaFuncAttributeMaxDynamicSharedMemorySize, gemm_smem);
    cudaFuncSetAttribute(hgemm_tc<2>,
                         cudaFuncAttributeMaxDynamicSharedMemorySize, gemm_smem);

    // 1) QKV projection + scatter
    hgemm_tc<1><<<dim3(N1 / 128, M1 / 128), 256, gemm_smem>>>(
        xh, wqkvh, bqkv, nullptr, N1);

    // 2) flash attention (R12-proven)
    const int attn_smem = 3 * 2 * KVT * (int)sizeof(unsigned);    // 61440
    cudaFuncSetAttribute(attn_kernel,
                         cudaFuncAttributeMaxDynamicSharedMemorySize, attn_smem);
    attn_kernel<<<dim3(HWDIM / 128, NPROB), 256, attn_smem>>>();

    // 3) output projection
    hgemm_tc<2><<<dim3(CDIM / 128, M1 / 128), 256, gemm_smem>>>(
        atth, wouth, bout, out, CDIM);
}

// round 16
// speedup vs baseline: 2.3054x; 1.0085x over previous
#include <cuda_runtime.h>
#include <cuda_fp16.h>
#include <math.h>
#include <stdint.h>

// Problem constants
#define M1    16384     // B*T*HW rows
#define CDIM  512
#define N1    1536      // 3*C
#define NH    8
#define HD    64
#define TT    16
#define HWDIM 1024
#define NPROB 128       // NH * TT
#define CU    256       // CDIM/2 (u32 half2 units)
#define HU    32        // HD/2
#define LOG2E 1.4426950408889634f

// Scratch. half2-packed u32. Q pair-interleaved; everything else quad layouts.
__device__ unsigned g_q[(size_t)NPROB * HWDIM * HU];   // [p][hw][il(d/2)], *log2e/8
__device__ unsigned g_k[(size_t)NPROB * 16 * 2048];    // [p][kt][quadK]
__device__ unsigned g_vt[(size_t)NPROB * 16 * 2048];   // [p][kt][quadV]
__device__ unsigned g_atth[(size_t)M1 * CU];           // quad-A
__device__ unsigned g_xh[(size_t)M1 * CU];             // quad-A
__device__ unsigned g_wqkvh[(size_t)N1 * CU];          // quad-B
__device__ unsigned g_wouth[(size_t)CDIM * CU];        // quad-B

// ---------------------------------------------------------------------------
// helpers
// ---------------------------------------------------------------------------
__device__ __forceinline__ unsigned packh2(float x, float y) {
    __half2 h = __floats2half2_rn(x, y);
    return *reinterpret_cast<unsigned*>(&h);
}

__device__ __forceinline__ void mma16(float c[4],
                                      unsigned a0, unsigned a1, unsigned a2,
                                      unsigned a3, unsigned b0, unsigned b1) {
    asm volatile(
        "mma.sync.aligned.m16n8k16.row.col.f32.f16.f16.f32 "
        "{%0,%1,%2,%3}, {%4,%5,%6,%7}, {%8,%9}, {%0,%1,%2,%3};\n"
        : "+f"(c[0]), "+f"(c[1]), "+f"(c[2]), "+f"(c[3])
        : "r"(a0), "r"(a1), "r"(a2), "r"(a3), "r"(b0), "r"(b1));
}

__device__ __forceinline__ unsigned smem_u32(const void* p) {
    return (unsigned)__cvta_generic_to_shared(p);
}
__device__ __forceinline__ void cp16(unsigned dst, const void* src) {
    asm volatile("cp.async.cg.shared.global [%0], [%1], 16;" :: "r"(dst), "l"(src));
}
__device__ __forceinline__ void cp_commit() {
    asm volatile("cp.async.commit_group;");
}
template <int N>
__device__ __forceinline__ void cp_wait() {
    asm volatile("cp.async.wait_group %0;" :: "n"(N));
}

// pair interleave (Q only): (t, t+4) -> (2t, 2t+1)
__device__ __forceinline__ int perm8(int j) {
    return ((j & 3) << 1) | ((j >> 2) & 1);
}
__device__ __forceinline__ int IL(int u) {
    return (u & ~7) | perm8(u & 7);
}

// ---- fragment-quad index functions ----
// A quad: {A[m][k0], A[m+8][k0], A[m][k0+4], A[m+8][k0+4]}
__device__ __forceinline__ int quadA_idx(int m, int ku) {
    int mb = m >> 7, ml = m & 127;
    int mt = ml >> 4, rh = (ml >> 3) & 1, gg = ml & 7;
    int kt = ku >> 5, kl = ku & 31;
    int ks = kl >> 3, rem = kl & 7;
    int kh = rem >> 2, tg = rem & 3;
    int q = ((ks * 4 + tg) * 8 + mt) * 8 + ((gg + 2 * tg) & 7);
    return (mb * 8 + kt) * 4096 + q * 4 + (rh + 2 * kh);
}
// B quad: {B[n][k0], B[n][k0+4], B[n+8][k0], B[n+8][k0+4]}
__device__ __forceinline__ int quadB_idx(int n, int ku) {
    int nb = n >> 7, nl = n & 127;
    int wn = nl >> 5, r = nl & 31;
    int j = r >> 4, rr = r & 15;
    int nh = (rr >> 3) & 1, gg = rr & 7;
    int kt = ku >> 5, kl = ku & 31;
    int ks = kl >> 3, rem = kl & 7;
    int kh = rem >> 2, tg = rem & 3;
    int q = ((ks * 4 + tg) * 8 + wn * 2 + j) * 8 + ((gg + 2 * tg) & 7);
    return (nb * 8 + kt) * 4096 + q * 4 + (nh * 2 + kh);
}
// K quad (per problem, per 64-key tile): keys as n, d-u32 as k
__device__ __forceinline__ int quadK_idx(int key, int ku) {   // key 0..1023, ku 0..31
    int kt = key >> 6, kz = key & 63;
    int j = kz >> 4, r = kz & 15;
    int keyh = (r >> 3) & 1, gg = r & 7;
    int ks = ku >> 3, rem = ku & 7;
    int dh = rem >> 2, tg = rem & 3;
    int q = ((ks * 4 + tg) * 4 + j) * 8 + ((gg + 2 * tg) & 7);
    return kt * 2048 + q * 4 + (keyh * 2 + dh);
}
// V quad: d as n, key-u32 as k
__device__ __forceinline__ int quadV_idx(int d, int keyu) {   // d 0..63, keyu 0..511
    int kt = keyu >> 5, kl = keyu & 31;
    int ks = kl >> 3, rem = kl & 7;
    int keyh = rem >> 2, tg = rem & 3;
    int j = d >> 4, r = d & 15;
    int dh = (r >> 3) & 1, gg = r & 7;
    int q = ((ks * 4 + tg) * 4 + j) * 8 + ((gg + 2 * tg) & 7);
    return kt * 2048 + q * 4 + (dh * 2 + keyh);
}

// ---------------------------------------------------------------------------
// prepass: pack x -> quad-A; transpose+pack weights -> quad-B
// ---------------------------------------------------------------------------
__global__ void pack_x_kernel(const float* __restrict__ in,
                              unsigned* __restrict__ out, int n4)
{
    int i = blockIdx.x * blockDim.x + threadIdx.x;
    if (i < n4) {
        float4 v = ((const float4*)in)[i];
        int m = i >> 7;                 // 128 float4 per 512-float row
        int ku0 = (2 * i) & 255;
        out[quadA_idx(m, ku0)]     = packh2(v.x, v.y);
        out[quadA_idx(m, ku0 + 1)] = packh2(v.z, v.w);
    }
}

__global__ __launch_bounds__(256) void transpack_kernel(
    const float* __restrict__ in, unsigned* __restrict__ out, int K, int N)
{
    __shared__ float t[64][33];
    int n0 = blockIdx.x * 32, k0 = blockIdx.y * 64;
#pragma unroll
    for (int i = 0; i < 8; ++i) {
        int idx = i * 256 + threadIdx.x;
        int r = idx >> 5, c = idx & 31;
        t[r][c] = in[(size_t)(k0 + r) * N + n0 + c];
    }
    __syncthreads();
#pragma unroll
    for (int i = 0; i < 4; ++i) {
        int idx = i * 256 + threadIdx.x;
        int nl = idx >> 5, j = idx & 31;
        out[quadB_idx(n0 + nl, (k0 >> 1) + j)] =
            packh2(t[2 * j][nl], t[2 * j + 1][nl]);
    }
}

// ---------------------------------------------------------------------------
// FP16 TC GEMM, quad layouts, LDS.128 fragments. K = 256 u32 fixed.
// Block 128x128, 8 warps, warp tile 64x32. 2-stage, single barrier/k-tile.
// EPI==1: QKV scatter (Q pair-interleaved; K/V quad layouts);
// EPI==2: Cout f32 = acc + bias.
// ---------------------------------------------------------------------------
__device__ __forceinline__ void g_issue(
    const unsigned* __restrict__ A, const unsigned* __restrict__ B,
    unsigned* sh, int tid, int kt, int buf, int mb, int nb)
{
    unsigned* Ad = sh + buf * 8192;
    unsigned* Bd = Ad + 4096;
    const unsigned* Ac = A + (size_t)(mb * 8 + kt) * 4096;
    const unsigned* Bc = B + (size_t)(nb * 8 + kt) * 4096;
#pragma unroll
    for (int i = 0; i < 8; ++i) {
        int idx = i * 256 + tid;
        if (idx < 1024) cp16(smem_u32(Ad + idx * 4), Ac + idx * 4);
        else            cp16(smem_u32(Bd + (idx - 1024) * 4), Bc + (idx - 1024) * 4);
    }
    cp_commit();
}

template <int EPI>
__global__ __launch_bounds__(256, 2) void hgemm_tc(
    const unsigned* __restrict__ A, const unsigned* __restrict__ B,
    const float* __restrict__ bias, float* __restrict__ Cout, int N)
{
    extern __shared__ unsigned sh[];

    const int tid  = threadIdx.x;
    const int warp = tid >> 5;
    const int lane = tid & 31;
    const int g    = lane >> 2;
    const int tg   = lane & 3;
    const int wm   = warp & 1;
    const int wn   = warp >> 1;
    const int mb   = blockIdx.y;
    const int nb   = blockIdx.x;
    const int swz  = (g + 2 * tg) & 7;

    float acc[4][4][4];
#pragma unroll
    for (int i = 0; i < 4; ++i)
#pragma unroll
        for (int j = 0; j < 4; ++j)
#pragma unroll
            for (int r = 0; r < 4; ++r) acc[i][j][r] = 0.0f;

    g_issue(A, B, sh, tid, 0, 0, mb, nb);

#pragma unroll
    for (int kt = 0; kt < 8; ++kt) {
        cp_wait<0>();
        __syncthreads();
        if (kt + 1 < 8)
            g_issue(A, B, sh, tid, kt + 1, (kt + 1) & 1, mb, nb);

        const unsigned* Ab = sh + (kt & 1) * 8192;
        const unsigned* Bb = Ab + 4096;
#pragma unroll
        for (int ks = 0; ks < 4; ++ks) {
            int bk = ks * 4 + tg;
            uint4 qa[4], qb[2];
#pragma unroll
            for (int mt = 0; mt < 4; ++mt)
                qa[mt] = *(const uint4*)(Ab + ((bk * 8 + wm * 4 + mt) * 8 + swz) * 4);
#pragma unroll
            for (int j = 0; j < 2; ++j)
                qb[j] = *(const uint4*)(Bb + ((bk * 8 + wn * 2 + j) * 8 + swz) * 4);
#pragma unroll
            for (int mt = 0; mt < 4; ++mt)
#pragma unroll
                for (int j = 0; j < 2; ++j) {
                    mma16(acc[mt][2 * j],     qa[mt].x, qa[mt].y, qa[mt].z, qa[mt].w,
                          qb[j].x, qb[j].y);
                    mma16(acc[mt][2 * j + 1], qa[mt].x, qa[mt].y, qa[mt].z, qa[mt].w,
                          qb[j].z, qb[j].w);
                }
        }
    }

    // ---- epilogue ----
    if (EPI == 1) {
#pragma unroll
        for (int mt = 0; mt < 4; ++mt) {
            int m  = mb * 128 + wm * 64 + mt * 16 + g;
            int t  = m >> 10;
            int hw0 = m & 1023;
            int hw1 = (m + 8) & 1023;
#pragma unroll
            for (int nt = 0; nt < 4; ++nt) {
                int n   = nb * 128 + wn * 32 + nt * 8 + 2 * tg;
                float2 bv = *(const float2*)(bias + n);
                int s   = n >> 9;           // warp-uniform
                int rem = n & 511;
                int h   = rem >> 6;
                int d   = rem & 63;         // even
                float v00 = acc[mt][nt][0] + bv.x;   // (hw0, d)
                float v01 = acc[mt][nt][1] + bv.y;   // (hw0, d+1)
                float v10 = acc[mt][nt][2] + bv.x;   // (hw1, d)
                float v11 = acc[mt][nt][3] + bv.y;   // (hw1, d+1)
                int p = h * 16 + t;
                if (s == 0) {
                    const float qs = 0.125f * LOG2E;   // exp2-domain softmax
                    int du = IL(d >> 1);
                    size_t base = (size_t)p * 1024 * HU + du;
                    g_q[base + (size_t)hw0 * HU] = packh2(v00 * qs, v01 * qs);
                    g_q[base + (size_t)hw1 * HU] = packh2(v10 * qs, v11 * qs);
                } else if (s == 1) {
                    size_t pb = (size_t)p * 32768;
                    g_k[pb + quadK_idx(hw0, d >> 1)] = packh2(v00, v01);
                    g_k[pb + quadK_idx(hw1, d >> 1)] = packh2(v10, v11);
                } else {
                    // V: transpose to [d][key-pair]; partner lane g^1 = row+1
                    float p00 = __shfl_xor_sync(0xFFFFFFFFu, v00, 4);
                    float p01 = __shfl_xor_sync(0xFFFFFFFFu, v01, 4);
                    float p10 = __shfl_xor_sync(0xFFFFFFFFu, v10, 4);
                    float p11 = __shfl_xor_sync(0xFFFFFFFFu, v11, 4);
                    if ((g & 1) == 0) {   // even rows own the pair (hw, hw+1)
                        size_t pb = (size_t)p * 32768;
                        g_vt[pb + quadV_idx(d,     hw0 >> 1)] = packh2(v00, p00);
                        g_vt[pb + quadV_idx(d + 1, hw0 >> 1)] = packh2(v01, p01);
                        g_vt[pb + quadV_idx(d,     hw1 >> 1)] = packh2(v10, p10);
                        g_vt[pb + quadV_idx(d + 1, hw1 >> 1)] = packh2(v11, p11);
                    }
                }
            }
        }
    } else {
#pragma unroll
        for (int mt = 0; mt < 4; ++mt) {
            int m = mb * 128 + wm * 64 + mt * 16 + g;
#pragma unroll
            for (int nt = 0; nt < 4; ++nt) {
                int n = nb * 128 + wn * 32 + nt * 8 + 2 * tg;
                float2 bv = *(const float2*)(bias + n);
                float2 v0, v1;
                v0.x = acc[mt][nt][0] + bv.x;
                v0.y = acc[mt][nt][1] + bv.y;
                v1.x = acc[mt][nt][2] + bv.x;
                v1.y = acc[mt][nt][3] + bv.y;
                *(float2*)(Cout + (size_t)m * N + n)       = v0;
                *(float2*)(Cout + (size_t)(m + 8) * N + n) = v1;
            }
        }
    }
}

// ---------------------------------------------------------------------------
// FP16 flash attention, exp2 softmax, quad K/V layouts (LDS.128 fragments).
// 256 thr / 8 warps; warp w owns q rows [w*16, w*16+16).
// 3-stage cp.async ring, one barrier per KV tile. Buffer = 4096 u32 (K+V).
// g_atth epilogue: quad-A with row = (h*1024+q)*2 + (t>>3), ku = (t&7)*32+uu.
// ---------------------------------------------------------------------------
__device__ __forceinline__ void attn_issue(
    const unsigned* __restrict__ Kg, const unsigned* __restrict__ Vtg,
    unsigned* sm, int tid, int kt, int buf)
{
    unsigned* Kd = sm + buf * 4096;
    unsigned* Vd = Kd + 2048;
    const unsigned* Kc = Kg + (size_t)kt * 2048;
    const unsigned* Vc = Vtg + (size_t)kt * 2048;
#pragma unroll
    for (int i = 0; i < 4; ++i) {
        int idx = i * 256 + tid;
        if (idx < 512) cp16(smem_u32(Kd + idx * 4), Kc + idx * 4);
        else           cp16(smem_u32(Vd + (idx - 512) * 4), Vc + (idx - 512) * 4);
    }
    cp_commit();
}

__global__ __launch_bounds__(256, 2) void attn_kernel()
{
    extern __shared__ unsigned sm[];

    const int p  = blockIdx.y;
    const int q0 = blockIdx.x * 128;
    const unsigned* Qg  = g_q  + (size_t)p * HWDIM * HU;
    const unsigned* Kg  = g_k  + (size_t)p * 32768;
    const unsigned* Vtg = g_vt + (size_t)p * 32768;

    const int tid  = threadIdx.x;
    const int w    = tid >> 5;
    const int lane = tid & 31;
    const int g    = lane >> 2;
    const int tg   = lane & 3;
    const int m    = w * 16 + g;
    const int swz  = (g + 2 * tg) & 7;

    attn_issue(Kg, Vtg, sm, tid, 0, 0);
    attn_issue(Kg, Vtg, sm, tid, 1, 1);

    // Q fragments (pair-interleaved gmem): one uint2 per (s,row)
    unsigned Qr[4][4];
    {
        const unsigned* Q0 = Qg + (size_t)(q0 + m) * HU;
        const unsigned* Q1 = Q0 + 8 * HU;
#pragma unroll
        for (int s = 0; s < 4; ++s) {
            uint2 qa = __ldg((const uint2*)(Q0 + s * 8 + 2 * tg));
            uint2 qb = __ldg((const uint2*)(Q1 + s * 8 + 2 * tg));
            Qr[s][0] = qa.x; Qr[s][2] = qa.y;
            Qr[s][1] = qb.x; Qr[s][3] = qb.y;
        }
    }

    float O[8][4];
#pragma unroll
    for (int nt = 0; nt < 8; ++nt)
#pragma unroll
        for (int r = 0; r < 4; ++r) O[nt][r] = 0.0f;
    float mo[2] = {-1e30f, -1e30f};
    float l[2]  = {0.0f, 0.0f};

    int bc = 0;   // compute buffer
    int bi = 2;   // issue buffer
    for (int kt = 0; kt < 16; ++kt) {
        if (kt + 1 < 16) cp_wait<1>(); else cp_wait<0>();
        __syncthreads();
        if (kt + 2 < 16)
            attn_issue(Kg, Vtg, sm, tid, kt + 2, bi);

        const unsigned* Kb = sm + bc * 4096;
        const unsigned* Vb = Kb + 2048;

        // ---- S = Q K^T (log2-domain scores) ----
        float S[8][4];
#pragma unroll
        for (int nk = 0; nk < 8; ++nk)
#pragma unroll
            for (int r = 0; r < 4; ++r) S[nk][r] = 0.0f;
#pragma unroll
        for (int ks = 0; ks < 4; ++ks) {
            int bk = ks * 4 + tg;
#pragma unroll
            for (int j = 0; j < 4; ++j) {
                uint4 kq = *(const uint4*)(Kb + ((bk * 4 + j) * 8 + swz) * 4);
                mma16(S[2 * j],     Qr[ks][0], Qr[ks][1], Qr[ks][2], Qr[ks][3],
                      kq.x, kq.y);
                mma16(S[2 * j + 1], Qr[ks][0], Qr[ks][1], Qr[ks][2], Qr[ks][3],
                      kq.z, kq.w);
            }
        }

        // ---- online softmax (rows m, m+8), exp2 domain ----
        float mn[2] = {-1e30f, -1e30f};
#pragma unroll
        for (int nk = 0; nk < 8; ++nk) {
            mn[0] = fmaxf(mn[0], fmaxf(S[nk][0], S[nk][1]));
            mn[1] = fmaxf(mn[1], fmaxf(S[nk][2], S[nk][3]));
        }
#pragma unroll
        for (int s = 0; s < 2; ++s) {
            mn[s] = fmaxf(mn[s], __shfl_xor_sync(0xFFFFFFFFu, mn[s], 1));
            mn[s] = fmaxf(mn[s], __shfl_xor_sync(0xFFFFFFFFu, mn[s], 2));
            mn[s] = fmaxf(mn[s], mo[s]);
        }
        float al[2];
        al[0] = exp2f(mo[0] - mn[0]);
        al[1] = exp2f(mo[1] - mn[1]);
#pragma unroll
        for (int nt = 0; nt < 8; ++nt) {
            O[nt][0] *= al[0]; O[nt][1] *= al[0];
            O[nt][2] *= al[1]; O[nt][3] *= al[1];
        }
        float rs[2] = {0.0f, 0.0f};
#pragma unroll
        for (int nk = 0; nk < 8; ++nk) {
            float p0 = exp2f(S[nk][0] - mn[0]);
            float p1 = exp2f(S[nk][1] - mn[0]);
            float p2 = exp2f(S[nk][2] - mn[1]);
            float p3 = exp2f(S[nk][3] - mn[1]);
            rs[0] += p0 + p1;
            rs[1] += p2 + p3;
            S[nk][0] = p0; S[nk][1] = p1; S[nk][2] = p2; S[nk][3] = p3;
        }
#pragma unroll
        for (int s = 0; s < 2; ++s) {
            rs[s] += __shfl_xor_sync(0xFFFFFFFFu, rs[s], 1);
            rs[s] += __shfl_xor_sync(0xFFFFFFFFu, rs[s], 2);
            l[s] = l[s] * al[s] + rs[s];
            mo[s] = mn[s];
        }

        // ---- O += P V : P packs directly from S registers ----
#pragma unroll
        for (int ks = 0; ks < 4; ++ks) {
            unsigned a0 = packh2(S[2 * ks][0],     S[2 * ks][1]);
            unsigned a1 = packh2(S[2 * ks][2],     S[2 * ks][3]);
            unsigned a2 = packh2(S[2 * ks + 1][0], S[2 * ks + 1][1]);
            unsigned a3 = packh2(S[2 * ks + 1][2], S[2 * ks + 1][3]);
            int bk = ks * 4 + tg;
#pragma unroll
            for (int j = 0; j < 4; ++j) {
                uint4 vq = *(const uint4*)(Vb + ((bk * 4 + j) * 8 + swz) * 4);
                mma16(O[2 * j],     a0, a1, a2, a3, vq.x, vq.y);
                mma16(O[2 * j + 1], a0, a1, a2, a3, vq.z, vq.w);
            }
        }

        bc = (bc == 2) ? 0 : bc + 1;
        bi = (bi == 2) ? 0 : bi + 1;
    }

    // ---- epilogue: normalize + pack + quad-A store (correct row/ku) ----
    const int h = p >> 4;
    const int t = p & 15;
    {
        int q = q0 + m;
        float inv0 = 1.0f / l[0];
        float inv1 = 1.0f / l[1];
        int row0 = (h * 1024 + q)     * 2 + (t >> 3);
        int row1 = (h * 1024 + q + 8) * 2 + (t >> 3);
        int kub  = (t & 7) * 32;
#pragma unroll
        for (int nt = 0; nt < 8; ++nt) {
            int ku = kub + nt * 4 + tg;
            g_atth[quadA_idx(row0, ku)] = packh2(O[nt][0] * inv0, O[nt][1] * inv0);
            g_atth[quadA_idx(row1, ku)] = packh2(O[nt][2] * inv1, O[nt][3] * inv1);
        }
    }
}

// ---------------------------------------------------------------------------
extern "C" void kernel_launch(void* const* d_in, const int* in_sizes, int n_in,
                              void* d_out, int out_size)
{
    const float* x    = (const float*)d_in[0];
    const float* Wqkv = (const float*)d_in[1];
    const float* bqkv = (const float*)d_in[2];
    const float* Wout = (const float*)d_in[3];
    const float* bout = (const float*)d_in[4];
    float* out = (float*)d_out;

    unsigned *xh, *wqkvh, *wouth, *atth;
    cudaGetSymbolAddress((void**)&xh, g_xh);
    cudaGetSymbolAddress((void**)&wqkvh, g_wqkvh);
    cudaGetSymbolAddress((void**)&wouth, g_wouth);
    cudaGetSymbolAddress((void**)&atth, g_atth);

    // 0) prepass: pack x -> quad-A; transpose+pack weights -> quad-B
    pack_x_kernel<<<(M1 * CDIM / 4 + 255) / 256, 256>>>(x, xh, M1 * CDIM / 4);
    transpack_kernel<<<dim3(N1 / 32, CDIM / 64), 256>>>(Wqkv, wqkvh, CDIM, N1);
    transpack_kernel<<<dim3(CDIM / 32, CDIM / 64), 256>>>(Wout, wouth, CDIM, CDIM);

    const int gemm_smem = 2 * 8192 * (int)sizeof(unsigned);   // 65536
    cudaFuncSetAttribute(hgemm_tc<1>,
                         cudaFuncAttributeMaxDynamicSharedMemorySize, gemm_smem);
    cudaFuncSetAttribute(hgemm_tc<2>,
                         cudaFuncAttributeMaxDynamicSharedMemorySize, gemm_smem);

    // 1) QKV projection + scatter
    hgemm_tc<1><<<dim3(N1 / 128, M1 / 128), 256, gemm_smem>>>(
        xh, wqkvh, bqkv, nullptr, N1);

    // 2) flash attention (quad K/V, 3-stage ring)
    const int attn_smem = 3 * 4096 * (int)sizeof(unsigned);   // 49152
    cudaFuncSetAttribute(attn_kernel,
                         cudaFuncAttributeMaxDynamicSharedMemorySize, attn_smem);
    attn_kernel<<<dim3(HWDIM / 128, NPROB), 256, attn_smem>>>();

    // 3) output projection
    hgemm_tc<2><<<dim3(CDIM / 128, M1 / 128), 256, gemm_smem>>>(
        atth, wouth, bout, out, CDIM);
}